// round 12
// baseline (speedup 1.0000x reference)
#include <cuda_runtime.h>
#include <cuda_bf16.h>
#include <math.h>
#include <stdint.h>

#define DI    1024
#define DH    2048
#define S_LEN 4096
#define BATCH 4
#define M_TOT (BATCH * S_LEN)   // 16384
#define N1    (3 * DH)          // 6144

#define OUT_ELEMS ((size_t)M_TOT * DI)
#define NH_OFF    OUT_ELEMS
#define NLH_OFF   (OUT_ELEMS + (size_t)BATCH * DH)

// ---------------- static scratch ------------------------------------------
__device__ float         g_C[(size_t)M_TOT * DH];
__device__ float         g_V[(size_t)M_TOT * DH];
__device__ __nv_bfloat16 g_Xhi[(size_t)M_TOT * DI];
__device__ __nv_bfloat16 g_Xlo[(size_t)M_TOT * DI];
__device__ __nv_bfloat16 g_W1Thi[(size_t)N1 * DI];   // [N1][DI]
__device__ __nv_bfloat16 g_W1Tlo[(size_t)N1 * DI];
__device__ __nv_bfloat16 g_Hhi[(size_t)M_TOT * DH];
__device__ __nv_bfloat16 g_Hlo[(size_t)M_TOT * DH];
__device__ __nv_bfloat16 g_W2Thi[(size_t)DI * DH];   // [DI][DH]
__device__ __nv_bfloat16 g_W2Tlo[(size_t)DI * DH];

// ---------------- math helpers --------------------------------------------
__device__ __forceinline__ float softplusf(float z) {
    return z > 15.f ? z : log1pf(__expf(z));
}
__device__ __forceinline__ float sigmoidf(float z) {
    return 1.f / (1.f + __expf(-z));
}
__device__ __forceinline__ float g_fn(float x) {
    return x >= 0.f ? x + 0.5f : sigmoidf(x);
}
__device__ __forceinline__ void splitf(float a, __nv_bfloat16& hi, __nv_bfloat16& lo) {
    __nv_bfloat16 h = __float2bfloat16(a);
    hi = h;
    lo = __float2bfloat16(a - __bfloat162float(h));
}

// ---------------- PTX helpers (sm_80-class; valid on plain sm_103) ---------
__device__ __forceinline__ uint32_t smem_u32(const void* p) {
    uint32_t a;
    asm("{ .reg .u64 t; cvta.to.shared.u64 t, %1; cvt.u32.u64 %0, t; }"
        : "=r"(a) : "l"(p));
    return a;
}
#define CP16(dst, src) \
    asm volatile("cp.async.cg.shared.global [%0], [%1], 16;" \
                 :: "r"(dst), "l"(src))
#define CP_COMMIT() asm volatile("cp.async.commit_group;" ::: "memory")
#define CP_WAIT0()  asm volatile("cp.async.wait_group 0;" ::: "memory")
#define CP_WAIT1()  asm volatile("cp.async.wait_group 1;" ::: "memory")

#define LDSM4(r, addr) \
    asm volatile("ldmatrix.sync.aligned.m8n8.x4.shared.b16 {%0,%1,%2,%3}, [%4];" \
        : "=r"((r)[0]), "=r"((r)[1]), "=r"((r)[2]), "=r"((r)[3]) : "r"(addr))

#define MMA16816(d, a, b0v, b1v) \
    asm volatile("mma.sync.aligned.m16n8k16.row.col.f32.bf16.bf16.f32 " \
        "{%0,%1,%2,%3}, {%4,%5,%6,%7}, {%8,%9}, {%0,%1,%2,%3};" \
        : "+f"((d)[0]), "+f"((d)[1]), "+f"((d)[2]), "+f"((d)[3]) \
        : "r"((a)[0]), "r"((a)[1]), "r"((a)[2]), "r"((a)[3]), \
          "r"(b0v), "r"(b1v))

// swizzle for 64-byte rows: XOR 16B-unit index (bits 4-5) with row bits (7-8)
__device__ __forceinline__ uint32_t swz64(uint32_t o) {
    return o ^ ((o >> 3) & 0x30);
}

// ---------------------------------------------------------------------------
// split X -> bf16 hi/lo
// ---------------------------------------------------------------------------
__global__ __launch_bounds__(256) void split_x_kernel(const float* __restrict__ X) {
    size_t i = (size_t)blockIdx.x * 256 + threadIdx.x;
    float4 v = reinterpret_cast<const float4*>(X)[i];
    __nv_bfloat16 h[4], l[4];
    splitf(v.x, h[0], l[0]); splitf(v.y, h[1], l[1]);
    splitf(v.z, h[2], l[2]); splitf(v.w, h[3], l[3]);
    *reinterpret_cast<uint2*>(&g_Xhi[i * 4]) = *reinterpret_cast<uint2*>(h);
    *reinterpret_cast<uint2*>(&g_Xlo[i * 4]) = *reinterpret_cast<uint2*>(l);
}

// ---------------------------------------------------------------------------
// transpose + split  W[R][C] -> T[C][R] bf16 hi/lo
// ---------------------------------------------------------------------------
__device__ __forceinline__ void tsplit_body(const float* __restrict__ W,
                                            __nv_bfloat16* __restrict__ Thi,
                                            __nv_bfloat16* __restrict__ Tlo,
                                            int R, int C) {
    __shared__ float t[32][33];
    int tx = threadIdx.x, ty = threadIdx.y;
    int c0 = blockIdx.x * 32, r0 = blockIdx.y * 32;
    #pragma unroll
    for (int j = 0; j < 32; j += 8)
        t[ty + j][tx] = W[(size_t)(r0 + ty + j) * C + c0 + tx];
    __syncthreads();
    #pragma unroll
    for (int j = 0; j < 32; j += 8) {
        float a = t[tx][ty + j];
        __nv_bfloat16 h, l; splitf(a, h, l);
        size_t o = (size_t)(c0 + ty + j) * R + r0 + tx;
        Thi[o] = h; Tlo[o] = l;
    }
}
__global__ __launch_bounds__(256) void tsplit_w1_kernel(const float* __restrict__ W1) {
    tsplit_body(W1, g_W1Thi, g_W1Tlo, DI, N1);
}
__global__ __launch_bounds__(256) void tsplit_w2_kernel(const float* __restrict__ W2) {
    tsplit_body(W2, g_W2Thi, g_W2Tlo, DH, DI);
}

// ---------------------------------------------------------------------------
// K1: proj = x@W1 (+b1, gate math fused) -> g_C, g_V
// block: 128m x (32 ch x 3 gates = 96n), BK=32, 2-stage cp.async, 256 thr
// smem per stage: Ahi 8K | Alo 8K | Bhi 6K | Blo 6K = 28672 B; x2 = 57344
// epilogue stages proj[128][100] f32 (51200 B, overlaid)
// ---------------------------------------------------------------------------
#define G1_STAGE 28672
#define G1_SMEM  57344

__global__ __launch_bounds__(256) void gemm1_mma_kernel(const float* __restrict__ b1) {
    extern __shared__ char sm[];
    const uint32_t sb = smem_u32(sm);
    const int tid = threadIdx.x, lane = tid & 31, wid = tid >> 5;
    const int wm = wid >> 1, wn = wid & 1;
    const int m0 = blockIdx.y * 128, cb0 = blockIdx.x * 32;

    float acc[2][6][4];
    #pragma unroll
    for (int i = 0; i < 2; i++)
        #pragma unroll
        for (int j = 0; j < 6; j++)
            #pragma unroll
            for (int k = 0; k < 4; k++) acc[i][j][k] = 0.f;

    // prefetch helper (macro to keep addresses simple)
    const int ur = tid >> 2, uc = tid & 3;          // A: rows via u>>2
    #define G1_PREFETCH(s, kt) do {                                            \
        uint32_t A0 = sb + (s) * G1_STAGE;                                     \
        uint32_t L0 = A0 + 8192, B0 = A0 + 16384, B1 = A0 + 22528;             \
        _Pragma("unroll")                                                      \
        for (int i = 0; i < 2; i++) {                                          \
            int r = ur + i * 64;                                               \
            uint32_t d = swz64((uint32_t)(r * 64 + uc * 16));                  \
            const __nv_bfloat16* gh = g_Xhi + (size_t)(m0 + r) * DI + (kt) + uc * 8; \
            const __nv_bfloat16* gl = g_Xlo + (size_t)(m0 + r) * DI + (kt) + uc * 8; \
            CP16(A0 + d, gh); CP16(L0 + d, gl);                                \
        }                                                                      \
        {                                                                      \
            int r = ur; int gate = r >> 5, chl = r & 31;                       \
            size_t row = (size_t)(gate * DH + cb0 + chl) * DI + (kt) + uc * 8; \
            uint32_t d = swz64((uint32_t)(r * 64 + uc * 16));                  \
            CP16(B0 + d, g_W1Thi + row); CP16(B1 + d, g_W1Tlo + row);          \
        }                                                                      \
        if (tid < 128) {                                                       \
            int r = ur + 64; int gate = r >> 5, chl = r & 31;                  \
            size_t row = (size_t)(gate * DH + cb0 + chl) * DI + (kt) + uc * 8; \
            uint32_t d = swz64((uint32_t)(r * 64 + uc * 16));                  \
            CP16(B0 + d, g_W1Thi + row); CP16(B1 + d, g_W1Tlo + row);          \
        }                                                                      \
    } while (0)

    G1_PREFETCH(0, 0);
    CP_COMMIT();

    const int arow = wm * 32 + (lane & 15);
    const int browb = wn * 48 + ((lane >> 4) << 3) + (lane & 7);

    for (int ck = 0; ck < 32; ck++) {
        if (ck + 1 < 32) {
            G1_PREFETCH((ck + 1) & 1, (ck + 1) * 32);
            CP_COMMIT();
            CP_WAIT1();
        } else {
            CP_WAIT0();
        }
        __syncthreads();

        const uint32_t A0 = sb + (ck & 1) * G1_STAGE;
        const uint32_t L0 = A0 + 8192, B0 = A0 + 16384, B1 = A0 + 22528;
        #pragma unroll
        for (int kk = 0; kk < 32; kk += 16) {
            const uint32_t acol = (uint32_t)(kk + (lane >> 4) * 8) * 2;
            const uint32_t bcol = (uint32_t)(kk + ((lane >> 3) & 1) * 8) * 2;
            #pragma unroll
            for (int p = 0; p < 3; p++) {
                const uint32_t Ab = (p == 2) ? L0 : A0;
                const uint32_t Bb = (p == 1) ? B1 : B0;
                uint32_t a[2][4];
                LDSM4(a[0], Ab + swz64((uint32_t)(arow * 64) + acol));
                LDSM4(a[1], Ab + swz64((uint32_t)((arow + 16) * 64) + acol));
                uint32_t b[3][4];
                #pragma unroll
                for (int j = 0; j < 3; j++)
                    LDSM4(b[j], Bb + swz64((uint32_t)((browb + j * 16) * 64) + bcol));
                #pragma unroll
                for (int tm = 0; tm < 2; tm++)
                    #pragma unroll
                    for (int tn = 0; tn < 6; tn++)
                        MMA16816(acc[tm][tn], a[tm],
                                 b[tn >> 1][(tn & 1) * 2], b[tn >> 1][(tn & 1) * 2 + 1]);
            }
        }
        __syncthreads();
    }

    // ---- epilogue: acc -> proj smem -> gate math -> g_C, g_V ----
    float* proj = reinterpret_cast<float*>(sm);     // [128][100]
    #pragma unroll
    for (int tm = 0; tm < 2; tm++)
        #pragma unroll
        for (int tn = 0; tn < 6; tn++) {
            int row = wm * 32 + tm * 16 + (lane >> 2);
            int col = wn * 48 + tn * 8 + 2 * (lane & 3);
            *reinterpret_cast<float2*>(&proj[row * 100 + col]) =
                make_float2(acc[tm][tn][0], acc[tm][tn][1]);
            *reinterpret_cast<float2*>(&proj[(row + 8) * 100 + col]) =
                make_float2(acc[tm][tn][2], acc[tm][tn][3]);
        }
    __syncthreads();

    const int ch = tid & 31;
    const int r0 = tid >> 5;
    const float bh = __ldg(&b1[cb0 + ch]);
    const float bf = __ldg(&b1[DH + cb0 + ch]);
    const float bi = __ldg(&b1[2 * DH + cb0 + ch]);
    #pragma unroll
    for (int i = 0; i < 16; i++) {
        int row = r0 + i * 8;
        float hid = proj[row * 100 + ch] + bh;
        float fg  = proj[row * 100 + 32 + ch] + bf;
        float ig  = proj[row * 100 + 64 + ch] + bi;
        float diff = softplusf(-fg) - softplusf(-ig);
        size_t o = (size_t)(m0 + row) * DH + cb0 + ch;
        g_C[o] = sigmoidf(-diff);
        g_V[o] = sigmoidf(diff) * g_fn(hid);
    }
    #undef G1_PREFETCH
}

// ---------------------------------------------------------------------------
// K2: sequential scan h_t = c_t*h_{t-1} + v_t; writes H hi/lo + out tails
// ---------------------------------------------------------------------------
__global__ __launch_bounds__(128) void scan_kernel(
    const float* __restrict__ initH, float* __restrict__ out)
{
    int gidx = blockIdx.x * 128 + threadIdx.x;
    int b = gidx >> 11;
    int d = gidx & (DH - 1);
    float h = g_fn(initH[d]);
    size_t base = (size_t)b * S_LEN * DH + d;
    #pragma unroll 8
    for (int s = 0; s < S_LEN; s++) {
        size_t idx = base + (size_t)s * DH;
        h = fmaf(g_C[idx], h, g_V[idx]);
        __nv_bfloat16 hh, hl; splitf(h, hh, hl);
        g_Hhi[idx] = hh; g_Hlo[idx] = hl;
    }
    out[NH_OFF  + (size_t)b * DH + d] = h;
    out[NLH_OFF + (size_t)b * DH + d] = logf(h);
}

// ---------------------------------------------------------------------------
// K3: out = h@W2 + b2
// block: 128m x 128n, BK=32, 2-stage cp.async, 256 thr
// smem per stage: Ahi 8K | Alo 8K | Bhi 8K | Blo 8K = 32768; x2 = 65536
// ---------------------------------------------------------------------------
#define G2_STAGE 32768
#define G2_SMEM  65536

__global__ __launch_bounds__(256) void gemm2_mma_kernel(
    const float* __restrict__ b2, float* __restrict__ out)
{
    extern __shared__ char sm[];
    const uint32_t sb = smem_u32(sm);
    const int tid = threadIdx.x, lane = tid & 31, wid = tid >> 5;
    const int wm = wid >> 1, wn = wid & 1;
    const int m0 = blockIdx.y * 128, n0 = blockIdx.x * 128;

    float acc[2][8][4];
    #pragma unroll
    for (int i = 0; i < 2; i++)
        #pragma unroll
        for (int j = 0; j < 8; j++)
            #pragma unroll
            for (int k = 0; k < 4; k++) acc[i][j][k] = 0.f;

    const int ur = tid >> 2, uc = tid & 3;
    #define G2_PREFETCH(s, kt) do {                                            \
        uint32_t A0 = sb + (s) * G2_STAGE;                                     \
        uint32_t L0 = A0 + 8192, B0 = A0 + 16384, B1 = A0 + 24576;             \
        _Pragma("unroll")                                                      \
        for (int i = 0; i < 2; i++) {                                          \
            int r = ur + i * 64;                                               \
            uint32_t d = swz64((uint32_t)(r * 64 + uc * 16));                  \
            CP16(A0 + d, g_Hhi  + (size_t)(m0 + r) * DH + (kt) + uc * 8);      \
            CP16(L0 + d, g_Hlo  + (size_t)(m0 + r) * DH + (kt) + uc * 8);      \
            CP16(B0 + d, g_W2Thi + (size_t)(n0 + r) * DH + (kt) + uc * 8);     \
            CP16(B1 + d, g_W2Tlo + (size_t)(n0 + r) * DH + (kt) + uc * 8);     \
        }                                                                      \
    } while (0)

    G2_PREFETCH(0, 0);
    CP_COMMIT();

    const int arow = wm * 32 + (lane & 15);
    const int browb = wn * 64 + ((lane >> 4) << 3) + (lane & 7);

    for (int ck = 0; ck < 64; ck++) {
        if (ck + 1 < 64) {
            G2_PREFETCH((ck + 1) & 1, (ck + 1) * 32);
            CP_COMMIT();
            CP_WAIT1();
        } else {
            CP_WAIT0();
        }
        __syncthreads();

        const uint32_t A0 = sb + (ck & 1) * G2_STAGE;
        const uint32_t L0 = A0 + 8192, B0 = A0 + 16384, B1 = A0 + 24576;
        #pragma unroll
        for (int kk = 0; kk < 32; kk += 16) {
            const uint32_t acol = (uint32_t)(kk + (lane >> 4) * 8) * 2;
            const uint32_t bcol = (uint32_t)(kk + ((lane >> 3) & 1) * 8) * 2;
            #pragma unroll
            for (int p = 0; p < 3; p++) {
                const uint32_t Ab = (p == 2) ? L0 : A0;
                const uint32_t Bb = (p == 1) ? B1 : B0;
                uint32_t a[2][4];
                LDSM4(a[0], Ab + swz64((uint32_t)(arow * 64) + acol));
                LDSM4(a[1], Ab + swz64((uint32_t)((arow + 16) * 64) + acol));
                uint32_t b[4][4];
                #pragma unroll
                for (int j = 0; j < 4; j++)
                    LDSM4(b[j], Bb + swz64((uint32_t)((browb + j * 16) * 64) + bcol));
                #pragma unroll
                for (int tm = 0; tm < 2; tm++)
                    #pragma unroll
                    for (int tn = 0; tn < 8; tn++)
                        MMA16816(acc[tm][tn], a[tm],
                                 b[tn >> 1][(tn & 1) * 2], b[tn >> 1][(tn & 1) * 2 + 1]);
            }
        }
        __syncthreads();
    }

    // ---- epilogue: + b2, direct stores ----
    #pragma unroll
    for (int tm = 0; tm < 2; tm++)
        #pragma unroll
        for (int tn = 0; tn < 8; tn++) {
            int row = m0 + wm * 32 + tm * 16 + (lane >> 2);
            int col = n0 + wn * 64 + tn * 8 + 2 * (lane & 3);
            float bb0 = __ldg(&b2[col]), bb1 = __ldg(&b2[col + 1]);
            *reinterpret_cast<float2*>(&out[(size_t)row * DI + col]) =
                make_float2(acc[tm][tn][0] + bb0, acc[tm][tn][1] + bb1);
            *reinterpret_cast<float2*>(&out[(size_t)(row + 8) * DI + col]) =
                make_float2(acc[tm][tn][2] + bb0, acc[tm][tn][3] + bb1);
        }
    #undef G2_PREFETCH
}

// ---------------------------------------------------------------------------
extern "C" void kernel_launch(void* const* d_in, const int* in_sizes, int n_in,
                              void* d_out, int out_size)
{
    const float* x     = (const float*)d_in[0];
    const float* W1    = (const float*)d_in[1];
    const float* b1    = (const float*)d_in[2];
    const float* W2    = (const float*)d_in[3];
    const float* b2    = (const float*)d_in[4];
    const float* initH = (const float*)d_in[5];
    float* out = (float*)d_out;

    cudaFuncSetAttribute(gemm1_mma_kernel,
                         cudaFuncAttributeMaxDynamicSharedMemorySize, G1_SMEM);
    cudaFuncSetAttribute(gemm2_mma_kernel,
                         cudaFuncAttributeMaxDynamicSharedMemorySize, G2_SMEM);

    split_x_kernel<<<(M_TOT * DI) / (4 * 256), 256>>>(x);
    tsplit_w1_kernel<<<dim3(N1 / 32, DI / 32), dim3(32, 8)>>>(W1);
    tsplit_w2_kernel<<<dim3(DI / 32, DH / 32), dim3(32, 8)>>>(W2);

    gemm1_mma_kernel<<<dim3(DH / 32, M_TOT / 128), 256, G1_SMEM>>>(b1);

    scan_kernel<<<(BATCH * DH) / 128, 128>>>(initH, out);

    gemm2_mma_kernel<<<dim3(DI / 128, M_TOT / 128), 256, G2_SMEM>>>(b2, out);
}

// round 13
// speedup vs baseline: 1.9458x; 1.9458x over previous
#include <cuda_runtime.h>
#include <cuda_bf16.h>
#include <math.h>
#include <stdint.h>

#define DI    1024
#define DH    2048
#define S_LEN 4096
#define BATCH 4
#define M_TOT (BATCH * S_LEN)   // 16384
#define N1    (3 * DH)          // 6144

#define OUT_ELEMS ((size_t)M_TOT * DI)
#define NH_OFF    OUT_ELEMS
#define NLH_OFF   (OUT_ELEMS + (size_t)BATCH * DH)

#define CHUNK 64
#define NCH   (S_LEN / CHUNK)   // 64
#define BD    (BATCH * DH)      // 8192

// ---------------- static scratch ------------------------------------------
__device__ float         g_C[(size_t)M_TOT * DH];
__device__ float         g_V[(size_t)M_TOT * DH];
__device__ __nv_bfloat16 g_Xhi[(size_t)M_TOT * DI];
__device__ __nv_bfloat16 g_Xlo[(size_t)M_TOT * DI];
__device__ __nv_bfloat16 g_W1Thi[(size_t)N1 * DI];   // [N1][DI]
__device__ __nv_bfloat16 g_W1Tlo[(size_t)N1 * DI];
__device__ __nv_bfloat16 g_Hhi[(size_t)M_TOT * DH];
__device__ __nv_bfloat16 g_Hlo[(size_t)M_TOT * DH];
__device__ __nv_bfloat16 g_W2Thi[(size_t)DI * DH];   // [DI][DH]
__device__ __nv_bfloat16 g_W2Tlo[(size_t)DI * DH];
// scan chunk scratch
__device__ float g_Ak [(size_t)NCH * BD];
__device__ float g_Bk [(size_t)NCH * BD];
__device__ float g_Hin[(size_t)NCH * BD];

// ---------------- math helpers --------------------------------------------
__device__ __forceinline__ float softplusf(float z) {
    return z > 15.f ? z : log1pf(__expf(z));
}
__device__ __forceinline__ float sigmoidf(float z) {
    return 1.f / (1.f + __expf(-z));
}
__device__ __forceinline__ float g_fn(float x) {
    return x >= 0.f ? x + 0.5f : sigmoidf(x);
}
__device__ __forceinline__ void splitf(float a, __nv_bfloat16& hi, __nv_bfloat16& lo) {
    __nv_bfloat16 h = __float2bfloat16(a);
    hi = h;
    lo = __float2bfloat16(a - __bfloat162float(h));
}

// ---------------- PTX helpers (sm_80-class; valid on plain sm_103) ---------
__device__ __forceinline__ uint32_t smem_u32(const void* p) {
    uint32_t a;
    asm("{ .reg .u64 t; cvta.to.shared.u64 t, %1; cvt.u32.u64 %0, t; }"
        : "=r"(a) : "l"(p));
    return a;
}
#define CP16(dst, src) \
    asm volatile("cp.async.cg.shared.global [%0], [%1], 16;" \
                 :: "r"(dst), "l"(src))
#define CP_COMMIT() asm volatile("cp.async.commit_group;" ::: "memory")
#define CP_WAIT0()  asm volatile("cp.async.wait_group 0;" ::: "memory")
#define CP_WAIT1()  asm volatile("cp.async.wait_group 1;" ::: "memory")

#define LDSM4(r, addr) \
    asm volatile("ldmatrix.sync.aligned.m8n8.x4.shared.b16 {%0,%1,%2,%3}, [%4];" \
        : "=r"((r)[0]), "=r"((r)[1]), "=r"((r)[2]), "=r"((r)[3]) : "r"(addr))

#define MMA16816(d, a, b0v, b1v) \
    asm volatile("mma.sync.aligned.m16n8k16.row.col.f32.bf16.bf16.f32 " \
        "{%0,%1,%2,%3}, {%4,%5,%6,%7}, {%8,%9}, {%0,%1,%2,%3};" \
        : "+f"((d)[0]), "+f"((d)[1]), "+f"((d)[2]), "+f"((d)[3]) \
        : "r"((a)[0]), "r"((a)[1]), "r"((a)[2]), "r"((a)[3]), \
          "r"(b0v), "r"(b1v))

__device__ __forceinline__ uint32_t swz64(uint32_t o) {
    return o ^ ((o >> 3) & 0x30);
}

// ---------------------------------------------------------------------------
// split X -> bf16 hi/lo
// ---------------------------------------------------------------------------
__global__ __launch_bounds__(256) void split_x_kernel(const float* __restrict__ X) {
    size_t i = (size_t)blockIdx.x * 256 + threadIdx.x;
    float4 v = reinterpret_cast<const float4*>(X)[i];
    __nv_bfloat16 h[4], l[4];
    splitf(v.x, h[0], l[0]); splitf(v.y, h[1], l[1]);
    splitf(v.z, h[2], l[2]); splitf(v.w, h[3], l[3]);
    *reinterpret_cast<uint2*>(&g_Xhi[i * 4]) = *reinterpret_cast<uint2*>(h);
    *reinterpret_cast<uint2*>(&g_Xlo[i * 4]) = *reinterpret_cast<uint2*>(l);
}

// ---------------------------------------------------------------------------
// transpose + split  W[R][C] -> T[C][R] bf16 hi/lo
// ---------------------------------------------------------------------------
__device__ __forceinline__ void tsplit_body(const float* __restrict__ W,
                                            __nv_bfloat16* __restrict__ Thi,
                                            __nv_bfloat16* __restrict__ Tlo,
                                            int R, int C) {
    __shared__ float t[32][33];
    int tx = threadIdx.x, ty = threadIdx.y;
    int c0 = blockIdx.x * 32, r0 = blockIdx.y * 32;
    #pragma unroll
    for (int j = 0; j < 32; j += 8)
        t[ty + j][tx] = W[(size_t)(r0 + ty + j) * C + c0 + tx];
    __syncthreads();
    #pragma unroll
    for (int j = 0; j < 32; j += 8) {
        float a = t[tx][ty + j];
        __nv_bfloat16 h, l; splitf(a, h, l);
        size_t o = (size_t)(c0 + ty + j) * R + r0 + tx;
        Thi[o] = h; Tlo[o] = l;
    }
}
__global__ __launch_bounds__(256) void tsplit_w1_kernel(const float* __restrict__ W1) {
    tsplit_body(W1, g_W1Thi, g_W1Tlo, DI, N1);
}
__global__ __launch_bounds__(256) void tsplit_w2_kernel(const float* __restrict__ W2) {
    tsplit_body(W2, g_W2Thi, g_W2Tlo, DH, DI);
}

// ---------------------------------------------------------------------------
// K1: proj = x@W1 (+b1, gate math fused) -> g_C, g_V
// block 128m x 96n, BK=32, 3-stage cp.async, 256 thr, hoisted LDSM
// stage: Ahi 8K | Alo 8K | Bhi 6K | Blo 6K = 28672 ; x3 = 86016
// ---------------------------------------------------------------------------
#define G1_STAGE 28672
#define G1_SMEM  (3 * G1_STAGE)

__global__ __launch_bounds__(256, 2) void gemm1_mma_kernel(const float* __restrict__ b1) {
    extern __shared__ char sm[];
    const uint32_t sb = smem_u32(sm);
    const int tid = threadIdx.x, lane = tid & 31, wid = tid >> 5;
    const int wm = wid >> 1, wn = wid & 1;
    const int m0 = blockIdx.y * 128, cb0 = blockIdx.x * 32;

    float acc[2][6][4];
    #pragma unroll
    for (int i = 0; i < 2; i++)
        #pragma unroll
        for (int j = 0; j < 6; j++)
            #pragma unroll
            for (int k = 0; k < 4; k++) acc[i][j][k] = 0.f;

    const int ur = tid >> 2, uc = tid & 3;
    #define G1_PREFETCH(s, kt) do {                                            \
        uint32_t A0 = sb + (s) * G1_STAGE;                                     \
        uint32_t L0 = A0 + 8192, B0 = A0 + 16384, B1 = A0 + 22528;             \
        _Pragma("unroll")                                                      \
        for (int i = 0; i < 2; i++) {                                          \
            int r = ur + i * 64;                                               \
            uint32_t d = swz64((uint32_t)(r * 64 + uc * 16));                  \
            CP16(A0 + d, g_Xhi + (size_t)(m0 + r) * DI + (kt) + uc * 8);       \
            CP16(L0 + d, g_Xlo + (size_t)(m0 + r) * DI + (kt) + uc * 8);       \
        }                                                                      \
        {                                                                      \
            int r = ur; int gate = r >> 5, chl = r & 31;                       \
            size_t row = (size_t)(gate * DH + cb0 + chl) * DI + (kt) + uc * 8; \
            uint32_t d = swz64((uint32_t)(r * 64 + uc * 16));                  \
            CP16(B0 + d, g_W1Thi + row); CP16(B1 + d, g_W1Tlo + row);          \
        }                                                                      \
        if (tid < 128) {                                                       \
            int r = ur + 64; int gate = r >> 5, chl = r & 31;                  \
            size_t row = (size_t)(gate * DH + cb0 + chl) * DI + (kt) + uc * 8; \
            uint32_t d = swz64((uint32_t)(r * 64 + uc * 16));                  \
            CP16(B0 + d, g_W1Thi + row); CP16(B1 + d, g_W1Tlo + row);          \
        }                                                                      \
    } while (0)

    G1_PREFETCH(0, 0);  CP_COMMIT();
    G1_PREFETCH(1, 32); CP_COMMIT();

    const int arow  = wm * 32 + (lane & 15);
    const int browb = wn * 48 + ((lane >> 4) << 3) + (lane & 7);

    for (int ck = 0; ck < 32; ck++) {
        CP_WAIT1();
        __syncthreads();
        if (ck + 2 < 32) G1_PREFETCH((ck + 2) % 3, (ck + 2) * 32);
        CP_COMMIT();

        const uint32_t A0 = sb + (ck % 3) * G1_STAGE;
        const uint32_t L0 = A0 + 8192, B0 = A0 + 16384, B1 = A0 + 22528;
        #pragma unroll
        for (int kk = 0; kk < 32; kk += 16) {
            const uint32_t acol = (uint32_t)(kk + (lane >> 4) * 8) * 2;
            const uint32_t bcol = (uint32_t)(kk + ((lane >> 3) & 1) * 8) * 2;
            uint32_t ahi[2][4], alo[2][4], bhi[3][4], blo[3][4];
            LDSM4(ahi[0], A0 + swz64((uint32_t)(arow * 64) + acol));
            LDSM4(ahi[1], A0 + swz64((uint32_t)((arow + 16) * 64) + acol));
            LDSM4(alo[0], L0 + swz64((uint32_t)(arow * 64) + acol));
            LDSM4(alo[1], L0 + swz64((uint32_t)((arow + 16) * 64) + acol));
            #pragma unroll
            for (int j = 0; j < 3; j++) {
                LDSM4(bhi[j], B0 + swz64((uint32_t)((browb + j * 16) * 64) + bcol));
                LDSM4(blo[j], B1 + swz64((uint32_t)((browb + j * 16) * 64) + bcol));
            }
            #pragma unroll
            for (int tm = 0; tm < 2; tm++)
                #pragma unroll
                for (int tn = 0; tn < 6; tn++) {
                    uint32_t* bh = &bhi[tn >> 1][(tn & 1) * 2];
                    uint32_t* bl = &blo[tn >> 1][(tn & 1) * 2];
                    MMA16816(acc[tm][tn], ahi[tm], bh[0], bh[1]);
                    MMA16816(acc[tm][tn], ahi[tm], bl[0], bl[1]);
                    MMA16816(acc[tm][tn], alo[tm], bh[0], bh[1]);
                }
        }
    }
    __syncthreads();

    // ---- epilogue: acc -> proj smem -> gate math -> g_C, g_V ----
    float* proj = reinterpret_cast<float*>(sm);     // [128][100]
    #pragma unroll
    for (int tm = 0; tm < 2; tm++)
        #pragma unroll
        for (int tn = 0; tn < 6; tn++) {
            int row = wm * 32 + tm * 16 + (lane >> 2);
            int col = wn * 48 + tn * 8 + 2 * (lane & 3);
            *reinterpret_cast<float2*>(&proj[row * 100 + col]) =
                make_float2(acc[tm][tn][0], acc[tm][tn][1]);
            *reinterpret_cast<float2*>(&proj[(row + 8) * 100 + col]) =
                make_float2(acc[tm][tn][2], acc[tm][tn][3]);
        }
    __syncthreads();

    const int ch = tid & 31;
    const int r0 = tid >> 5;
    const float bh = __ldg(&b1[cb0 + ch]);
    const float bf = __ldg(&b1[DH + cb0 + ch]);
    const float bi = __ldg(&b1[2 * DH + cb0 + ch]);
    #pragma unroll
    for (int i = 0; i < 16; i++) {
        int row = r0 + i * 8;
        float hid = proj[row * 100 + ch] + bh;
        float fg  = proj[row * 100 + 32 + ch] + bf;
        float ig  = proj[row * 100 + 64 + ch] + bi;
        float diff = softplusf(-fg) - softplusf(-ig);
        size_t o = (size_t)(m0 + row) * DH + cb0 + ch;
        g_C[o] = sigmoidf(-diff);
        g_V[o] = sigmoidf(diff) * g_fn(hid);
    }
    #undef G1_PREFETCH
}

// ---------------------------------------------------------------------------
// Parallel scan over S in 3 phases (chunk size 64)
// ---------------------------------------------------------------------------
__global__ __launch_bounds__(256) void scan_chunk_kernel() {
    int t = blockIdx.x * 256 + threadIdx.x;          // chunk*BD + bd
    int bd = t & (BD - 1);
    int chunk = t >> 13;
    int b = bd >> 11, d = bd & (DH - 1);
    size_t base = ((size_t)b * S_LEN + (size_t)chunk * CHUNK) * DH + d;
    float A = 1.f, Bv = 0.f;
    #pragma unroll 8
    for (int s = 0; s < CHUNK; s++) {
        size_t idx = base + (size_t)s * DH;
        float c = g_C[idx], v = g_V[idx];
        A *= c;
        Bv = fmaf(c, Bv, v);
    }
    g_Ak[t] = A; g_Bk[t] = Bv;
}

__global__ __launch_bounds__(256) void scan_carry_kernel(
    const float* __restrict__ initH, float* __restrict__ out)
{
    int bd = blockIdx.x * 256 + threadIdx.x;         // 0..8191 == b*DH+d
    int d = bd & (DH - 1);
    float h = g_fn(initH[d]);
    #pragma unroll 8
    for (int ch = 0; ch < NCH; ch++) {
        int t = ch * BD + bd;
        g_Hin[t] = h;
        h = fmaf(g_Ak[t], h, g_Bk[t]);
    }
    out[NH_OFF  + bd] = h;
    out[NLH_OFF + bd] = logf(h);
}

__global__ __launch_bounds__(256) void scan_emit_kernel() {
    int t = blockIdx.x * 256 + threadIdx.x;
    int bd = t & (BD - 1);
    int chunk = t >> 13;
    int b = bd >> 11, d = bd & (DH - 1);
    size_t base = ((size_t)b * S_LEN + (size_t)chunk * CHUNK) * DH + d;
    float h = g_Hin[t];
    #pragma unroll 8
    for (int s = 0; s < CHUNK; s++) {
        size_t idx = base + (size_t)s * DH;
        h = fmaf(g_C[idx], h, g_V[idx]);
        __nv_bfloat16 hh, hl; splitf(h, hh, hl);
        g_Hhi[idx] = hh; g_Hlo[idx] = hl;
    }
}

// ---------------------------------------------------------------------------
// K3: out = h@W2 + b2
// block 128m x 128n, BK=32, 3-stage cp.async, 256 thr
// stage: Ahi 8K | Alo 8K | Bhi 8K | Blo 8K = 32768 ; x3 = 98304
// ---------------------------------------------------------------------------
#define G2_STAGE 32768
#define G2_SMEM  (3 * G2_STAGE)

__global__ __launch_bounds__(256, 2) void gemm2_mma_kernel(
    const float* __restrict__ b2, float* __restrict__ out)
{
    extern __shared__ char sm[];
    const uint32_t sb = smem_u32(sm);
    const int tid = threadIdx.x, lane = tid & 31, wid = tid >> 5;
    const int wm = wid >> 1, wn = wid & 1;
    const int m0 = blockIdx.y * 128, n0 = blockIdx.x * 128;

    float acc[2][8][4];
    #pragma unroll
    for (int i = 0; i < 2; i++)
        #pragma unroll
        for (int j = 0; j < 8; j++)
            #pragma unroll
            for (int k = 0; k < 4; k++) acc[i][j][k] = 0.f;

    const int ur = tid >> 2, uc = tid & 3;
    #define G2_PREFETCH(s, kt) do {                                            \
        uint32_t A0 = sb + (s) * G2_STAGE;                                     \
        uint32_t L0 = A0 + 8192, B0 = A0 + 16384, B1 = A0 + 24576;             \
        _Pragma("unroll")                                                      \
        for (int i = 0; i < 2; i++) {                                          \
            int r = ur + i * 64;                                               \
            uint32_t d = swz64((uint32_t)(r * 64 + uc * 16));                  \
            CP16(A0 + d, g_Hhi  + (size_t)(m0 + r) * DH + (kt) + uc * 8);      \
            CP16(L0 + d, g_Hlo  + (size_t)(m0 + r) * DH + (kt) + uc * 8);      \
            CP16(B0 + d, g_W2Thi + (size_t)(n0 + r) * DH + (kt) + uc * 8);     \
            CP16(B1 + d, g_W2Tlo + (size_t)(n0 + r) * DH + (kt) + uc * 8);     \
        }                                                                      \
    } while (0)

    G2_PREFETCH(0, 0);  CP_COMMIT();
    G2_PREFETCH(1, 32); CP_COMMIT();

    const int arow  = wm * 32 + (lane & 15);
    const int browb = wn * 64 + ((lane >> 4) << 3) + (lane & 7);

    for (int ck = 0; ck < 64; ck++) {
        CP_WAIT1();
        __syncthreads();
        if (ck + 2 < 64) G2_PREFETCH((ck + 2) % 3, (ck + 2) * 32);
        CP_COMMIT();

        const uint32_t A0 = sb + (ck % 3) * G2_STAGE;
        const uint32_t L0 = A0 + 8192, B0 = A0 + 16384, B1 = A0 + 24576;
        #pragma unroll
        for (int kk = 0; kk < 32; kk += 16) {
            const uint32_t acol = (uint32_t)(kk + (lane >> 4) * 8) * 2;
            const uint32_t bcol = (uint32_t)(kk + ((lane >> 3) & 1) * 8) * 2;
            uint32_t ahi[2][4], alo[2][4], b[4][4];
            LDSM4(ahi[0], A0 + swz64((uint32_t)(arow * 64) + acol));
            LDSM4(ahi[1], A0 + swz64((uint32_t)((arow + 16) * 64) + acol));
            LDSM4(alo[0], L0 + swz64((uint32_t)(arow * 64) + acol));
            LDSM4(alo[1], L0 + swz64((uint32_t)((arow + 16) * 64) + acol));
            // pass hi*Bhi and lo*Bhi (Bhi loaded once)
            #pragma unroll
            for (int j = 0; j < 4; j++)
                LDSM4(b[j], B0 + swz64((uint32_t)((browb + j * 16) * 64) + bcol));
            #pragma unroll
            for (int tm = 0; tm < 2; tm++)
                #pragma unroll
                for (int tn = 0; tn < 8; tn++) {
                    uint32_t* bb = &b[tn >> 1][(tn & 1) * 2];
                    MMA16816(acc[tm][tn], ahi[tm], bb[0], bb[1]);
                    MMA16816(acc[tm][tn], alo[tm], bb[0], bb[1]);
                }
            // pass hi*Blo
            #pragma unroll
            for (int j = 0; j < 4; j++)
                LDSM4(b[j], B1 + swz64((uint32_t)((browb + j * 16) * 64) + bcol));
            #pragma unroll
            for (int tm = 0; tm < 2; tm++)
                #pragma unroll
                for (int tn = 0; tn < 8; tn++) {
                    uint32_t* bb = &b[tn >> 1][(tn & 1) * 2];
                    MMA16816(acc[tm][tn], ahi[tm], bb[0], bb[1]);
                }
        }
    }

    // ---- epilogue: + b2, direct stores ----
    #pragma unroll
    for (int tm = 0; tm < 2; tm++)
        #pragma unroll
        for (int tn = 0; tn < 8; tn++) {
            int row = m0 + wm * 32 + tm * 16 + (lane >> 2);
            int col = n0 + wn * 64 + tn * 8 + 2 * (lane & 3);
            float bb0 = __ldg(&b2[col]), bb1 = __ldg(&b2[col + 1]);
            *reinterpret_cast<float2*>(&out[(size_t)row * DI + col]) =
                make_float2(acc[tm][tn][0] + bb0, acc[tm][tn][1] + bb1);
            *reinterpret_cast<float2*>(&out[(size_t)(row + 8) * DI + col]) =
                make_float2(acc[tm][tn][2] + bb0, acc[tm][tn][3] + bb1);
        }
    #undef G2_PREFETCH
}

// ---------------------------------------------------------------------------
extern "C" void kernel_launch(void* const* d_in, const int* in_sizes, int n_in,
                              void* d_out, int out_size)
{
    const float* x     = (const float*)d_in[0];
    const float* W1    = (const float*)d_in[1];
    const float* b1    = (const float*)d_in[2];
    const float* W2    = (const float*)d_in[3];
    const float* b2    = (const float*)d_in[4];
    const float* initH = (const float*)d_in[5];
    float* out = (float*)d_out;

    cudaFuncSetAttribute(gemm1_mma_kernel,
                         cudaFuncAttributeMaxDynamicSharedMemorySize, G1_SMEM);
    cudaFuncSetAttribute(gemm2_mma_kernel,
                         cudaFuncAttributeMaxDynamicSharedMemorySize, G2_SMEM);

    split_x_kernel<<<(M_TOT * DI) / (4 * 256), 256>>>(x);
    tsplit_w1_kernel<<<dim3(N1 / 32, DI / 32), dim3(32, 8)>>>(W1);
    tsplit_w2_kernel<<<dim3(DI / 32, DH / 32), dim3(32, 8)>>>(W2);

    gemm1_mma_kernel<<<dim3(DH / 32, M_TOT / 128), 256, G1_SMEM>>>(b1);

    scan_chunk_kernel<<<(NCH * BD) / 256, 256>>>();
    scan_carry_kernel<<<BD / 256, 256>>>(initH, out);
    scan_emit_kernel<<<(NCH * BD) / 256, 256>>>();

    gemm2_mma_kernel<<<dim3(DI / 128, M_TOT / 128), 256, G2_SMEM>>>(b2, out);
}

// round 14
// speedup vs baseline: 1.9460x; 1.0001x over previous
#include <cuda_runtime.h>
#include <cuda_bf16.h>
#include <math.h>
#include <stdint.h>

#define DI    1024
#define DH    2048
#define S_LEN 4096
#define BATCH 4
#define M_TOT (BATCH * S_LEN)   // 16384
#define N1    (3 * DH)          // 6144

#define OUT_ELEMS ((size_t)M_TOT * DI)
#define NH_OFF    OUT_ELEMS
#define NLH_OFF   (OUT_ELEMS + (size_t)BATCH * DH)

#define CHUNK 64
#define NCH   (S_LEN / CHUNK)   // 64
#define BD    (BATCH * DH)      // 8192

// ---------------- static scratch ------------------------------------------
__device__ float         g_C[(size_t)M_TOT * DH];
__device__ float         g_V[(size_t)M_TOT * DH];
__device__ __nv_bfloat16 g_Xhi[(size_t)M_TOT * DI];
__device__ __nv_bfloat16 g_Xlo[(size_t)M_TOT * DI];
__device__ __nv_bfloat16 g_W1Thi[(size_t)N1 * DI];   // [N1][DI]
__device__ __nv_bfloat16 g_W1Tlo[(size_t)N1 * DI];
__device__ __nv_bfloat16 g_Hhi[(size_t)M_TOT * DH];
__device__ __nv_bfloat16 g_Hlo[(size_t)M_TOT * DH];
__device__ __nv_bfloat16 g_W2Thi[(size_t)DI * DH];   // [DI][DH]
__device__ __nv_bfloat16 g_W2Tlo[(size_t)DI * DH];
// scan chunk scratch
__device__ float g_Ak [(size_t)NCH * BD];
__device__ float g_Bk [(size_t)NCH * BD];
__device__ float g_Hin[(size_t)NCH * BD];

// ---------------- math helpers --------------------------------------------
__device__ __forceinline__ float softplusf(float z) {
    return z > 15.f ? z : log1pf(__expf(z));
}
__device__ __forceinline__ float sigmoidf(float z) {
    return 1.f / (1.f + __expf(-z));
}
__device__ __forceinline__ float g_fn(float x) {
    return x >= 0.f ? x + 0.5f : sigmoidf(x);
}
__device__ __forceinline__ void splitf(float a, __nv_bfloat16& hi, __nv_bfloat16& lo) {
    __nv_bfloat16 h = __float2bfloat16(a);
    hi = h;
    lo = __float2bfloat16(a - __bfloat162float(h));
}

// ---------------- PTX helpers (sm_80-class; valid on plain sm_103) ---------
__device__ __forceinline__ uint32_t smem_u32(const void* p) {
    uint32_t a;
    asm("{ .reg .u64 t; cvta.to.shared.u64 t, %1; cvt.u32.u64 %0, t; }"
        : "=r"(a) : "l"(p));
    return a;
}
#define CP16(dst, src) \
    asm volatile("cp.async.cg.shared.global [%0], [%1], 16;" \
                 :: "r"(dst), "l"(src))
#define CP_COMMIT() asm volatile("cp.async.commit_group;" ::: "memory")
#define CP_WAIT0()  asm volatile("cp.async.wait_group 0;" ::: "memory")
#define CP_WAIT1()  asm volatile("cp.async.wait_group 1;" ::: "memory")

#define LDSM4(r, addr) \
    asm volatile("ldmatrix.sync.aligned.m8n8.x4.shared.b16 {%0,%1,%2,%3}, [%4];" \
        : "=r"((r)[0]), "=r"((r)[1]), "=r"((r)[2]), "=r"((r)[3]) : "r"(addr))

#define MMA16816(d, a, b0v, b1v) \
    asm volatile("mma.sync.aligned.m16n8k16.row.col.f32.bf16.bf16.f32 " \
        "{%0,%1,%2,%3}, {%4,%5,%6,%7}, {%8,%9}, {%0,%1,%2,%3};" \
        : "+f"((d)[0]), "+f"((d)[1]), "+f"((d)[2]), "+f"((d)[3]) \
        : "r"((a)[0]), "r"((a)[1]), "r"((a)[2]), "r"((a)[3]), \
          "r"(b0v), "r"(b1v))

__device__ __forceinline__ uint32_t swz64(uint32_t o) {
    return o ^ ((o >> 3) & 0x30);
}

// ---------------------------------------------------------------------------
// split X -> bf16 hi/lo
// ---------------------------------------------------------------------------
__global__ __launch_bounds__(256) void split_x_kernel(const float* __restrict__ X) {
    size_t i = (size_t)blockIdx.x * 256 + threadIdx.x;
    float4 v = reinterpret_cast<const float4*>(X)[i];
    __nv_bfloat16 h[4], l[4];
    splitf(v.x, h[0], l[0]); splitf(v.y, h[1], l[1]);
    splitf(v.z, h[2], l[2]); splitf(v.w, h[3], l[3]);
    *reinterpret_cast<uint2*>(&g_Xhi[i * 4]) = *reinterpret_cast<uint2*>(h);
    *reinterpret_cast<uint2*>(&g_Xlo[i * 4]) = *reinterpret_cast<uint2*>(l);
}

// ---------------------------------------------------------------------------
// transpose + split  W[R][C] -> T[C][R] bf16 hi/lo
// ---------------------------------------------------------------------------
__device__ __forceinline__ void tsplit_body(const float* __restrict__ W,
                                            __nv_bfloat16* __restrict__ Thi,
                                            __nv_bfloat16* __restrict__ Tlo,
                                            int R, int C) {
    __shared__ float t[32][33];
    int tx = threadIdx.x, ty = threadIdx.y;
    int c0 = blockIdx.x * 32, r0 = blockIdx.y * 32;
    #pragma unroll
    for (int j = 0; j < 32; j += 8)
        t[ty + j][tx] = W[(size_t)(r0 + ty + j) * C + c0 + tx];
    __syncthreads();
    #pragma unroll
    for (int j = 0; j < 32; j += 8) {
        float a = t[tx][ty + j];
        __nv_bfloat16 h, l; splitf(a, h, l);
        size_t o = (size_t)(c0 + ty + j) * R + r0 + tx;
        Thi[o] = h; Tlo[o] = l;
    }
}
__global__ __launch_bounds__(256) void tsplit_w1_kernel(const float* __restrict__ W1) {
    tsplit_body(W1, g_W1Thi, g_W1Tlo, DI, N1);
}
__global__ __launch_bounds__(256) void tsplit_w2_kernel(const float* __restrict__ W2) {
    tsplit_body(W2, g_W2Thi, g_W2Tlo, DH, DI);
}

// ---------------------------------------------------------------------------
// K1: proj = x@W1 (+b1, gate math fused) -> g_C, g_V
// block 128m x 96n, BK=32, 3-stage cp.async, 256 thr, hoisted LDSM
// stage: Ahi 8K | Alo 8K | Bhi 6K | Blo 6K = 28672 ; x3 = 86016
// ---------------------------------------------------------------------------
#define G1_STAGE 28672
#define G1_SMEM  (3 * G1_STAGE)

__global__ __launch_bounds__(256, 2) void gemm1_mma_kernel(const float* __restrict__ b1) {
    extern __shared__ char sm[];
    const uint32_t sb = smem_u32(sm);
    const int tid = threadIdx.x, lane = tid & 31, wid = tid >> 5;
    const int wm = wid >> 1, wn = wid & 1;
    const int m0 = blockIdx.y * 128, cb0 = blockIdx.x * 32;

    float acc[2][6][4];
    #pragma unroll
    for (int i = 0; i < 2; i++)
        #pragma unroll
        for (int j = 0; j < 6; j++)
            #pragma unroll
            for (int k = 0; k < 4; k++) acc[i][j][k] = 0.f;

    const int ur = tid >> 2, uc = tid & 3;
    #define G1_PREFETCH(s, kt) do {                                            \
        uint32_t A0 = sb + (s) * G1_STAGE;                                     \
        uint32_t L0 = A0 + 8192, B0 = A0 + 16384, B1 = A0 + 22528;             \
        _Pragma("unroll")                                                      \
        for (int i = 0; i < 2; i++) {                                          \
            int r = ur + i * 64;                                               \
            uint32_t d = swz64((uint32_t)(r * 64 + uc * 16));                  \
            CP16(A0 + d, g_Xhi + (size_t)(m0 + r) * DI + (kt) + uc * 8);       \
            CP16(L0 + d, g_Xlo + (size_t)(m0 + r) * DI + (kt) + uc * 8);       \
        }                                                                      \
        {                                                                      \
            int r = ur; int gate = r >> 5, chl = r & 31;                       \
            size_t row = (size_t)(gate * DH + cb0 + chl) * DI + (kt) + uc * 8; \
            uint32_t d = swz64((uint32_t)(r * 64 + uc * 16));                  \
            CP16(B0 + d, g_W1Thi + row); CP16(B1 + d, g_W1Tlo + row);          \
        }                                                                      \
        if (tid < 128) {                                                       \
            int r = ur + 64; int gate = r >> 5, chl = r & 31;                  \
            size_t row = (size_t)(gate * DH + cb0 + chl) * DI + (kt) + uc * 8; \
            uint32_t d = swz64((uint32_t)(r * 64 + uc * 16));                  \
            CP16(B0 + d, g_W1Thi + row); CP16(B1 + d, g_W1Tlo + row);          \
        }                                                                      \
    } while (0)

    G1_PREFETCH(0, 0);  CP_COMMIT();
    G1_PREFETCH(1, 32); CP_COMMIT();

    const int arow  = wm * 32 + (lane & 15);
    const int browb = wn * 48 + ((lane >> 4) << 3) + (lane & 7);

    for (int ck = 0; ck < 32; ck++) {
        CP_WAIT1();
        __syncthreads();
        if (ck + 2 < 32) G1_PREFETCH((ck + 2) % 3, (ck + 2) * 32);
        CP_COMMIT();

        const uint32_t A0 = sb + (ck % 3) * G1_STAGE;
        const uint32_t L0 = A0 + 8192, B0 = A0 + 16384, B1 = A0 + 22528;
        #pragma unroll
        for (int kk = 0; kk < 32; kk += 16) {
            const uint32_t acol = (uint32_t)(kk + (lane >> 4) * 8) * 2;
            const uint32_t bcol = (uint32_t)(kk + ((lane >> 3) & 1) * 8) * 2;
            uint32_t ahi[2][4], alo[2][4], bhi[3][4], blo[3][4];
            LDSM4(ahi[0], A0 + swz64((uint32_t)(arow * 64) + acol));
            LDSM4(ahi[1], A0 + swz64((uint32_t)((arow + 16) * 64) + acol));
            LDSM4(alo[0], L0 + swz64((uint32_t)(arow * 64) + acol));
            LDSM4(alo[1], L0 + swz64((uint32_t)((arow + 16) * 64) + acol));
            #pragma unroll
            for (int j = 0; j < 3; j++) {
                LDSM4(bhi[j], B0 + swz64((uint32_t)((browb + j * 16) * 64) + bcol));
                LDSM4(blo[j], B1 + swz64((uint32_t)((browb + j * 16) * 64) + bcol));
            }
            #pragma unroll
            for (int tm = 0; tm < 2; tm++)
                #pragma unroll
                for (int tn = 0; tn < 6; tn++) {
                    uint32_t* bh = &bhi[tn >> 1][(tn & 1) * 2];
                    uint32_t* bl = &blo[tn >> 1][(tn & 1) * 2];
                    MMA16816(acc[tm][tn], ahi[tm], bh[0], bh[1]);
                    MMA16816(acc[tm][tn], ahi[tm], bl[0], bl[1]);
                    MMA16816(acc[tm][tn], alo[tm], bh[0], bh[1]);
                }
        }
    }
    __syncthreads();

    // ---- epilogue: acc -> proj smem -> gate math -> g_C, g_V ----
    float* proj = reinterpret_cast<float*>(sm);     // [128][100]
    #pragma unroll
    for (int tm = 0; tm < 2; tm++)
        #pragma unroll
        for (int tn = 0; tn < 6; tn++) {
            int row = wm * 32 + tm * 16 + (lane >> 2);
            int col = wn * 48 + tn * 8 + 2 * (lane & 3);
            *reinterpret_cast<float2*>(&proj[row * 100 + col]) =
                make_float2(acc[tm][tn][0], acc[tm][tn][1]);
            *reinterpret_cast<float2*>(&proj[(row + 8) * 100 + col]) =
                make_float2(acc[tm][tn][2], acc[tm][tn][3]);
        }
    __syncthreads();

    const int ch = tid & 31;
    const int r0 = tid >> 5;
    const float bh = __ldg(&b1[cb0 + ch]);
    const float bf = __ldg(&b1[DH + cb0 + ch]);
    const float bi = __ldg(&b1[2 * DH + cb0 + ch]);
    #pragma unroll
    for (int i = 0; i < 16; i++) {
        int row = r0 + i * 8;
        float hid = proj[row * 100 + ch] + bh;
        float fg  = proj[row * 100 + 32 + ch] + bf;
        float ig  = proj[row * 100 + 64 + ch] + bi;
        float diff = softplusf(-fg) - softplusf(-ig);
        size_t o = (size_t)(m0 + row) * DH + cb0 + ch;
        g_C[o] = sigmoidf(-diff);
        g_V[o] = sigmoidf(diff) * g_fn(hid);
    }
    #undef G1_PREFETCH
}

// ---------------------------------------------------------------------------
// Parallel scan over S in 3 phases (chunk size 64)
// ---------------------------------------------------------------------------
__global__ __launch_bounds__(256) void scan_chunk_kernel() {
    int t = blockIdx.x * 256 + threadIdx.x;          // chunk*BD + bd
    int bd = t & (BD - 1);
    int chunk = t >> 13;
    int b = bd >> 11, d = bd & (DH - 1);
    size_t base = ((size_t)b * S_LEN + (size_t)chunk * CHUNK) * DH + d;
    float A = 1.f, Bv = 0.f;
    #pragma unroll 8
    for (int s = 0; s < CHUNK; s++) {
        size_t idx = base + (size_t)s * DH;
        float c = g_C[idx], v = g_V[idx];
        A *= c;
        Bv = fmaf(c, Bv, v);
    }
    g_Ak[t] = A; g_Bk[t] = Bv;
}

__global__ __launch_bounds__(256) void scan_carry_kernel(
    const float* __restrict__ initH, float* __restrict__ out)
{
    int bd = blockIdx.x * 256 + threadIdx.x;         // 0..8191 == b*DH+d
    int d = bd & (DH - 1);
    float h = g_fn(initH[d]);
    #pragma unroll 8
    for (int ch = 0; ch < NCH; ch++) {
        int t = ch * BD + bd;
        g_Hin[t] = h;
        h = fmaf(g_Ak[t], h, g_Bk[t]);
    }
    out[NH_OFF  + bd] = h;
    out[NLH_OFF + bd] = logf(h);
}

__global__ __launch_bounds__(256) void scan_emit_kernel() {
    int t = blockIdx.x * 256 + threadIdx.x;
    int bd = t & (BD - 1);
    int chunk = t >> 13;
    int b = bd >> 11, d = bd & (DH - 1);
    size_t base = ((size_t)b * S_LEN + (size_t)chunk * CHUNK) * DH + d;
    float h = g_Hin[t];
    #pragma unroll 8
    for (int s = 0; s < CHUNK; s++) {
        size_t idx = base + (size_t)s * DH;
        h = fmaf(g_C[idx], h, g_V[idx]);
        __nv_bfloat16 hh, hl; splitf(h, hh, hl);
        g_Hhi[idx] = hh; g_Hlo[idx] = hl;
    }
}

// ---------------------------------------------------------------------------
// K3: out = h@W2 + b2
// block 128m x 128n, BK=32, 3-stage cp.async, 256 thr
// stage: Ahi 8K | Alo 8K | Bhi 8K | Blo 8K = 32768 ; x3 = 98304
// ---------------------------------------------------------------------------
#define G2_STAGE 32768
#define G2_SMEM  (3 * G2_STAGE)

__global__ __launch_bounds__(256, 2) void gemm2_mma_kernel(
    const float* __restrict__ b2, float* __restrict__ out)
{
    extern __shared__ char sm[];
    const uint32_t sb = smem_u32(sm);
    const int tid = threadIdx.x, lane = tid & 31, wid = tid >> 5;
    const int wm = wid >> 1, wn = wid & 1;
    const int m0 = blockIdx.y * 128, n0 = blockIdx.x * 128;

    float acc[2][8][4];
    #pragma unroll
    for (int i = 0; i < 2; i++)
        #pragma unroll
        for (int j = 0; j < 8; j++)
            #pragma unroll
            for (int k = 0; k < 4; k++) acc[i][j][k] = 0.f;

    const int ur = tid >> 2, uc = tid & 3;
    #define G2_PREFETCH(s, kt) do {                                            \
        uint32_t A0 = sb + (s) * G2_STAGE;                                     \
        uint32_t L0 = A0 + 8192, B0 = A0 + 16384, B1 = A0 + 24576;             \
        _Pragma("unroll")                                                      \
        for (int i = 0; i < 2; i++) {                                          \
            int r = ur + i * 64;                                               \
            uint32_t d = swz64((uint32_t)(r * 64 + uc * 16));                  \
            CP16(A0 + d, g_Hhi  + (size_t)(m0 + r) * DH + (kt) + uc * 8);      \
            CP16(L0 + d, g_Hlo  + (size_t)(m0 + r) * DH + (kt) + uc * 8);      \
            CP16(B0 + d, g_W2Thi + (size_t)(n0 + r) * DH + (kt) + uc * 8);     \
            CP16(B1 + d, g_W2Tlo + (size_t)(n0 + r) * DH + (kt) + uc * 8);     \
        }                                                                      \
    } while (0)

    G2_PREFETCH(0, 0);  CP_COMMIT();
    G2_PREFETCH(1, 32); CP_COMMIT();

    const int arow  = wm * 32 + (lane & 15);
    const int browb = wn * 64 + ((lane >> 4) << 3) + (lane & 7);

    for (int ck = 0; ck < 64; ck++) {
        CP_WAIT1();
        __syncthreads();
        if (ck + 2 < 64) G2_PREFETCH((ck + 2) % 3, (ck + 2) * 32);
        CP_COMMIT();

        const uint32_t A0 = sb + (ck % 3) * G2_STAGE;
        const uint32_t L0 = A0 + 8192, B0 = A0 + 16384, B1 = A0 + 24576;
        #pragma unroll
        for (int kk = 0; kk < 32; kk += 16) {
            const uint32_t acol = (uint32_t)(kk + (lane >> 4) * 8) * 2;
            const uint32_t bcol = (uint32_t)(kk + ((lane >> 3) & 1) * 8) * 2;
            uint32_t ahi[2][4], alo[2][4], b[4][4];
            LDSM4(ahi[0], A0 + swz64((uint32_t)(arow * 64) + acol));
            LDSM4(ahi[1], A0 + swz64((uint32_t)((arow + 16) * 64) + acol));
            LDSM4(alo[0], L0 + swz64((uint32_t)(arow * 64) + acol));
            LDSM4(alo[1], L0 + swz64((uint32_t)((arow + 16) * 64) + acol));
            // pass hi*Bhi and lo*Bhi (Bhi loaded once)
            #pragma unroll
            for (int j = 0; j < 4; j++)
                LDSM4(b[j], B0 + swz64((uint32_t)((browb + j * 16) * 64) + bcol));
            #pragma unroll
            for (int tm = 0; tm < 2; tm++)
                #pragma unroll
                for (int tn = 0; tn < 8; tn++) {
                    uint32_t* bb = &b[tn >> 1][(tn & 1) * 2];
                    MMA16816(acc[tm][tn], ahi[tm], bb[0], bb[1]);
                    MMA16816(acc[tm][tn], alo[tm], bb[0], bb[1]);
                }
            // pass hi*Blo
            #pragma unroll
            for (int j = 0; j < 4; j++)
                LDSM4(b[j], B1 + swz64((uint32_t)((browb + j * 16) * 64) + bcol));
            #pragma unroll
            for (int tm = 0; tm < 2; tm++)
                #pragma unroll
                for (int tn = 0; tn < 8; tn++) {
                    uint32_t* bb = &b[tn >> 1][(tn & 1) * 2];
                    MMA16816(acc[tm][tn], ahi[tm], bb[0], bb[1]);
                }
        }
    }

    // ---- epilogue: + b2, direct stores ----
    #pragma unroll
    for (int tm = 0; tm < 2; tm++)
        #pragma unroll
        for (int tn = 0; tn < 8; tn++) {
            int row = m0 + wm * 32 + tm * 16 + (lane >> 2);
            int col = n0 + wn * 64 + tn * 8 + 2 * (lane & 3);
            float bb0 = __ldg(&b2[col]), bb1 = __ldg(&b2[col + 1]);
            *reinterpret_cast<float2*>(&out[(size_t)row * DI + col]) =
                make_float2(acc[tm][tn][0] + bb0, acc[tm][tn][1] + bb1);
            *reinterpret_cast<float2*>(&out[(size_t)(row + 8) * DI + col]) =
                make_float2(acc[tm][tn][2] + bb0, acc[tm][tn][3] + bb1);
        }
    #undef G2_PREFETCH
}

// ---------------------------------------------------------------------------
extern "C" void kernel_launch(void* const* d_in, const int* in_sizes, int n_in,
                              void* d_out, int out_size)
{
    const float* x     = (const float*)d_in[0];
    const float* W1    = (const float*)d_in[1];
    const float* b1    = (const float*)d_in[2];
    const float* W2    = (const float*)d_in[3];
    const float* b2    = (const float*)d_in[4];
    const float* initH = (const float*)d_in[5];
    float* out = (float*)d_out;

    cudaFuncSetAttribute(gemm1_mma_kernel,
                         cudaFuncAttributeMaxDynamicSharedMemorySize, G1_SMEM);
    cudaFuncSetAttribute(gemm2_mma_kernel,
                         cudaFuncAttributeMaxDynamicSharedMemorySize, G2_SMEM);

    split_x_kernel<<<(M_TOT * DI) / (4 * 256), 256>>>(x);
    tsplit_w1_kernel<<<dim3(N1 / 32, DI / 32), dim3(32, 8)>>>(W1);
    tsplit_w2_kernel<<<dim3(DI / 32, DH / 32), dim3(32, 8)>>>(W2);

    gemm1_mma_kernel<<<dim3(DH / 32, M_TOT / 128), 256, G1_SMEM>>>(b1);

    scan_chunk_kernel<<<(NCH * BD) / 256, 256>>>();
    scan_carry_kernel<<<BD / 256, 256>>>(initH, out);
    scan_emit_kernel<<<(NCH * BD) / 256, 256>>>();

    gemm2_mma_kernel<<<dim3(DI / 128, M_TOT / 128), 256, G2_SMEM>>>(b2, out);
}

// round 15
// speedup vs baseline: 2.1309x; 1.0950x over previous
#include <cuda_runtime.h>
#include <cuda_bf16.h>
#include <math.h>
#include <stdint.h>

#define DI    1024
#define DH    2048
#define S_LEN 4096
#define BATCH 4
#define M_TOT (BATCH * S_LEN)   // 16384
#define N1    (3 * DH)          // 6144

#define OUT_ELEMS ((size_t)M_TOT * DI)
#define NH_OFF    OUT_ELEMS
#define NLH_OFF   (OUT_ELEMS + (size_t)BATCH * DH)

#define CHUNK 64
#define NCH   (S_LEN / CHUNK)   // 64
#define BD    (BATCH * DH)      // 8192

// ---------------- static scratch ------------------------------------------
__device__ float         g_C[(size_t)M_TOT * DH];
__device__ float         g_V[(size_t)M_TOT * DH];
__device__ __nv_bfloat16 g_Xhi[(size_t)M_TOT * DI];
__device__ __nv_bfloat16 g_Xlo[(size_t)M_TOT * DI];
__device__ __nv_bfloat16 g_W1Thi[(size_t)N1 * DI];   // [N1][DI]
__device__ __nv_bfloat16 g_W1Tlo[(size_t)N1 * DI];
__device__ __nv_bfloat16 g_Hhi[(size_t)M_TOT * DH];
__device__ __nv_bfloat16 g_Hlo[(size_t)M_TOT * DH];
__device__ __nv_bfloat16 g_W2Thi[(size_t)DI * DH];   // [DI][DH]
__device__ __nv_bfloat16 g_W2Tlo[(size_t)DI * DH];
// scan scratch
__device__ float g_Ak [(size_t)NCH * BD];
__device__ float g_Bk [(size_t)NCH * BD];
__device__ float g_Hin[(size_t)NCH * BD];

// ---------------- math helpers --------------------------------------------
__device__ __forceinline__ float softplusf(float z) {
    return z > 15.f ? z : log1pf(__expf(z));
}
__device__ __forceinline__ float sigmoidf(float z) {
    return 1.f / (1.f + __expf(-z));
}
__device__ __forceinline__ float g_fn(float x) {
    return x >= 0.f ? x + 0.5f : sigmoidf(x);
}
__device__ __forceinline__ void splitf(float a, __nv_bfloat16& hi, __nv_bfloat16& lo) {
    __nv_bfloat16 h = __float2bfloat16(a);
    hi = h;
    lo = __float2bfloat16(a - __bfloat162float(h));
}

// ---------------- PTX helpers ----------------------------------------------
__device__ __forceinline__ uint32_t smem_u32(const void* p) {
    uint32_t a;
    asm("{ .reg .u64 t; cvta.to.shared.u64 t, %1; cvt.u32.u64 %0, t; }"
        : "=r"(a) : "l"(p));
    return a;
}
#define CP16(dst, src) \
    asm volatile("cp.async.cg.shared.global [%0], [%1], 16;" \
                 :: "r"(dst), "l"(src))
#define CP_COMMIT() asm volatile("cp.async.commit_group;" ::: "memory")
#define CP_WAIT0()  asm volatile("cp.async.wait_group 0;" ::: "memory")
#define CP_WAIT1()  asm volatile("cp.async.wait_group 1;" ::: "memory")

#define LDSM4(r, addr) \
    asm volatile("ldmatrix.sync.aligned.m8n8.x4.shared.b16 {%0,%1,%2,%3}, [%4];" \
        : "=r"((r)[0]), "=r"((r)[1]), "=r"((r)[2]), "=r"((r)[3]) : "r"(addr))

#define MMA16816(d, a, b0v, b1v) \
    asm volatile("mma.sync.aligned.m16n8k16.row.col.f32.bf16.bf16.f32 " \
        "{%0,%1,%2,%3}, {%4,%5,%6,%7}, {%8,%9}, {%0,%1,%2,%3};" \
        : "+f"((d)[0]), "+f"((d)[1]), "+f"((d)[2]), "+f"((d)[3]) \
        : "r"((a)[0]), "r"((a)[1]), "r"((a)[2]), "r"((a)[3]), \
          "r"(b0v), "r"(b1v))

__device__ __forceinline__ uint32_t swz64(uint32_t o)  { return o ^ ((o >> 3) & 0x30); }
__device__ __forceinline__ uint32_t swz128(uint32_t o) { return o ^ ((o >> 3) & 0x70); }

// ---------------------------------------------------------------------------
// split X -> bf16 hi/lo
// ---------------------------------------------------------------------------
__global__ __launch_bounds__(256) void split_x_kernel(const float* __restrict__ X) {
    size_t i = (size_t)blockIdx.x * 256 + threadIdx.x;
    float4 v = reinterpret_cast<const float4*>(X)[i];
    __nv_bfloat16 h[4], l[4];
    splitf(v.x, h[0], l[0]); splitf(v.y, h[1], l[1]);
    splitf(v.z, h[2], l[2]); splitf(v.w, h[3], l[3]);
    *reinterpret_cast<uint2*>(&g_Xhi[i * 4]) = *reinterpret_cast<uint2*>(h);
    *reinterpret_cast<uint2*>(&g_Xlo[i * 4]) = *reinterpret_cast<uint2*>(l);
}

// ---------------------------------------------------------------------------
// transpose + split  W[R][C] -> T[C][R] bf16 hi/lo
// ---------------------------------------------------------------------------
__device__ __forceinline__ void tsplit_body(const float* __restrict__ W,
                                            __nv_bfloat16* __restrict__ Thi,
                                            __nv_bfloat16* __restrict__ Tlo,
                                            int R, int C) {
    __shared__ float t[32][33];
    int tx = threadIdx.x, ty = threadIdx.y;
    int c0 = blockIdx.x * 32, r0 = blockIdx.y * 32;
    #pragma unroll
    for (int j = 0; j < 32; j += 8)
        t[ty + j][tx] = W[(size_t)(r0 + ty + j) * C + c0 + tx];
    __syncthreads();
    #pragma unroll
    for (int j = 0; j < 32; j += 8) {
        float a = t[tx][ty + j];
        __nv_bfloat16 h, l; splitf(a, h, l);
        size_t o = (size_t)(c0 + ty + j) * R + r0 + tx;
        Thi[o] = h; Tlo[o] = l;
    }
}
__global__ __launch_bounds__(256) void tsplit_w1_kernel(const float* __restrict__ W1) {
    tsplit_body(W1, g_W1Thi, g_W1Tlo, DI, N1);
}
__global__ __launch_bounds__(256) void tsplit_w2_kernel(const float* __restrict__ W2) {
    tsplit_body(W2, g_W2Thi, g_W2Tlo, DH, DI);
}

// ---------------------------------------------------------------------------
// K1: proj = x@W1 (+b1, gate math, chunk-scan fused) -> g_C, g_V, g_Ak, g_Bk
// block 128m x 96n, BK=64, 2-stage cp.async, 256 thr
// stage: Ahi 16K | Alo 16K | Bhi 12K | Blo 12K = 57344 ; x2 = 114688
// ---------------------------------------------------------------------------
#define G1_STAGE 57344
#define G1_SMEM  (2 * G1_STAGE)

__global__ __launch_bounds__(256, 2) void gemm1_mma_kernel(const float* __restrict__ b1) {
    extern __shared__ char sm[];
    const uint32_t sb = smem_u32(sm);
    const int tid = threadIdx.x, lane = tid & 31, wid = tid >> 5;
    const int wm = wid >> 1, wn = wid & 1;
    const int m0 = blockIdx.y * 128, cb0 = blockIdx.x * 32;

    float acc[2][6][4];
    #pragma unroll
    for (int i = 0; i < 2; i++)
        #pragma unroll
        for (int j = 0; j < 6; j++)
            #pragma unroll
            for (int k = 0; k < 4; k++) acc[i][j][k] = 0.f;

    #define G1_PREFETCH(s, kt) do {                                            \
        uint32_t A0_ = sb + (s) * G1_STAGE;                                    \
        uint32_t L0_ = A0_ + 16384, B0_ = A0_ + 32768, B1_ = A0_ + 45056;      \
        _Pragma("unroll")                                                      \
        for (int i = 0; i < 4; i++) {                                          \
            int idx = tid + i * 256;                                           \
            int r = idx >> 3, c = idx & 7;                                     \
            uint32_t d = swz128((uint32_t)(r * 128 + c * 16));                 \
            CP16(A0_ + d, g_Xhi + (size_t)(m0 + r) * DI + (kt) + c * 8);       \
            CP16(L0_ + d, g_Xlo + (size_t)(m0 + r) * DI + (kt) + c * 8);       \
        }                                                                      \
        _Pragma("unroll")                                                      \
        for (int i = 0; i < 3; i++) {                                          \
            int idx = tid + i * 256;                                           \
            int r = idx >> 3, c = idx & 7;                                     \
            int gate = r >> 5, chl = r & 31;                                   \
            size_t row = (size_t)(gate * DH + cb0 + chl) * DI + (kt) + c * 8;  \
            uint32_t d = swz128((uint32_t)(r * 128 + c * 16));                 \
            CP16(B0_ + d, g_W1Thi + row); CP16(B1_ + d, g_W1Tlo + row);        \
        }                                                                      \
    } while (0)

    G1_PREFETCH(0, 0);
    CP_COMMIT();

    const int arow  = wm * 32 + (lane & 15);
    const int browb = wn * 48 + ((lane >> 4) << 3) + (lane & 7);

    for (int ck = 0; ck < 16; ck++) {
        CP_WAIT0();                 // stage ck data complete (only group in flight)
        __syncthreads();            // all warps done with buffer (ck+1)&1 from iter ck-1
        if (ck + 1 < 16) {
            G1_PREFETCH((ck + 1) & 1, (ck + 1) * 64);
            CP_COMMIT();
        }
        const uint32_t A0 = sb + (ck & 1) * G1_STAGE;
        const uint32_t L0 = A0 + 16384, B0 = A0 + 32768, B1 = A0 + 45056;
        #pragma unroll
        for (int kk = 0; kk < 64; kk += 16) {
            const uint32_t acol = (uint32_t)(kk + (lane >> 4) * 8) * 2;
            const uint32_t bcol = (uint32_t)(kk + ((lane >> 3) & 1) * 8) * 2;
            uint32_t ahi[2][4], alo[2][4], bhi[3][4], blo[3][4];
            LDSM4(ahi[0], A0 + swz128((uint32_t)(arow * 128) + acol));
            LDSM4(ahi[1], A0 + swz128((uint32_t)((arow + 16) * 128) + acol));
            LDSM4(alo[0], L0 + swz128((uint32_t)(arow * 128) + acol));
            LDSM4(alo[1], L0 + swz128((uint32_t)((arow + 16) * 128) + acol));
            #pragma unroll
            for (int j = 0; j < 3; j++) {
                LDSM4(bhi[j], B0 + swz128((uint32_t)((browb + j * 16) * 128) + bcol));
                LDSM4(blo[j], B1 + swz128((uint32_t)((browb + j * 16) * 128) + bcol));
            }
            #pragma unroll
            for (int tm = 0; tm < 2; tm++)
                #pragma unroll
                for (int tn = 0; tn < 6; tn++) {
                    uint32_t* bh = &bhi[tn >> 1][(tn & 1) * 2];
                    uint32_t* bl = &blo[tn >> 1][(tn & 1) * 2];
                    MMA16816(acc[tm][tn], ahi[tm], bh[0], bh[1]);
                    MMA16816(acc[tm][tn], ahi[tm], bl[0], bl[1]);
                    MMA16816(acc[tm][tn], alo[tm], bh[0], bh[1]);
                }
        }
    }
    __syncthreads();

    // ---- epilogue: acc -> proj smem -> gate math -> g_C/g_V + chunk scan ----
    float* proj = reinterpret_cast<float*>(sm);     // [128][100] = 51200 B
    #pragma unroll
    for (int tm = 0; tm < 2; tm++)
        #pragma unroll
        for (int tn = 0; tn < 6; tn++) {
            int row = wm * 32 + tm * 16 + (lane >> 2);
            int col = wn * 48 + tn * 8 + 2 * (lane & 3);
            *reinterpret_cast<float2*>(&proj[row * 100 + col]) =
                make_float2(acc[tm][tn][0], acc[tm][tn][1]);
            *reinterpret_cast<float2*>(&proj[(row + 8) * 100 + col]) =
                make_float2(acc[tm][tn][2], acc[tm][tn][3]);
        }
    __syncthreads();

    const int ch = tid & 31;
    const int seg = tid >> 5;                        // 8 segments of 16 rows
    const float bh = __ldg(&b1[cb0 + ch]);
    const float bf = __ldg(&b1[DH + cb0 + ch]);
    const float bi = __ldg(&b1[2 * DH + cb0 + ch]);
    float Aa = 1.f, Bb = 0.f;
    #pragma unroll
    for (int j = 0; j < 16; j++) {
        int row = seg * 16 + j;                      // sequential in time
        float hid = proj[row * 100 + ch] + bh;
        float fg  = proj[row * 100 + 32 + ch] + bf;
        float ig  = proj[row * 100 + 64 + ch] + bi;
        float diff = softplusf(-fg) - softplusf(-ig);
        float c = sigmoidf(-diff);
        float v = sigmoidf(diff) * g_fn(hid);
        size_t o = (size_t)(m0 + row) * DH + cb0 + ch;
        g_C[o] = c;
        g_V[o] = v;
        Aa *= c;
        Bb = fmaf(c, Bb, v);
    }
    float* pA = reinterpret_cast<float*>(sm + 51200);   // [8][32]
    float* pB = pA + 256;
    pA[seg * 32 + ch] = Aa;
    pB[seg * 32 + ch] = Bb;
    __syncthreads();
    if (tid < 64) {
        int cl = tid >> 5, c2 = tid & 31;            // 2 chunks x 32 channels
        float A = 1.f, Bv = 0.f;
        #pragma unroll
        for (int s2 = 0; s2 < 4; s2++) {
            int i2 = (cl * 4 + s2) * 32 + c2;
            float As = pA[i2], Bs = pB[i2];
            A = As * A;
            Bv = fmaf(As, Bv, Bs);
        }
        int b     = m0 / S_LEN;
        int chunk = (m0 % S_LEN) / CHUNK + cl;
        size_t t = (size_t)chunk * BD + (size_t)b * DH + cb0 + c2;
        g_Ak[t] = A;
        g_Bk[t] = Bv;
    }
    #undef G1_PREFETCH
}

// ---------------------------------------------------------------------------
// scan carry + emit
// ---------------------------------------------------------------------------
__global__ __launch_bounds__(256) void scan_carry_kernel(
    const float* __restrict__ initH, float* __restrict__ out)
{
    int bd = blockIdx.x * 256 + threadIdx.x;         // b*DH + d
    int d = bd & (DH - 1);
    float h = g_fn(initH[d]);
    #pragma unroll 8
    for (int ch = 0; ch < NCH; ch++) {
        int t = ch * BD + bd;
        g_Hin[t] = h;
        h = fmaf(g_Ak[t], h, g_Bk[t]);
    }
    out[NH_OFF  + bd] = h;
    out[NLH_OFF + bd] = logf(h);
}

__global__ __launch_bounds__(256) void scan_emit_kernel() {
    int t = blockIdx.x * 256 + threadIdx.x;
    int bd = t & (BD - 1);
    int chunk = t >> 13;
    int b = bd >> 11, d = bd & (DH - 1);
    size_t base = ((size_t)b * S_LEN + (size_t)chunk * CHUNK) * DH + d;
    float h = g_Hin[t];
    #pragma unroll 8
    for (int s = 0; s < CHUNK; s++) {
        size_t idx = base + (size_t)s * DH;
        h = fmaf(g_C[idx], h, g_V[idx]);
        __nv_bfloat16 hh, hl; splitf(h, hh, hl);
        g_Hhi[idx] = hh; g_Hlo[idx] = hl;
    }
}

// ---------------------------------------------------------------------------
// K3: out = h@W2 + b2
// block 128m x 128n, BK=32, 3-stage cp.async, 256 thr
// ---------------------------------------------------------------------------
#define G2_STAGE 32768
#define G2_SMEM  (3 * G2_STAGE)

__global__ __launch_bounds__(256, 2) void gemm2_mma_kernel(
    const float* __restrict__ b2, float* __restrict__ out)
{
    extern __shared__ char sm[];
    const uint32_t sb = smem_u32(sm);
    const int tid = threadIdx.x, lane = tid & 31, wid = tid >> 5;
    const int wm = wid >> 1, wn = wid & 1;
    const int m0 = blockIdx.y * 128, n0 = blockIdx.x * 128;

    float acc[2][8][4];
    #pragma unroll
    for (int i = 0; i < 2; i++)
        #pragma unroll
        for (int j = 0; j < 8; j++)
            #pragma unroll
            for (int k = 0; k < 4; k++) acc[i][j][k] = 0.f;

    const int ur = tid >> 2, uc = tid & 3;
    #define G2_PREFETCH(s, kt) do {                                            \
        uint32_t A0 = sb + (s) * G2_STAGE;                                     \
        uint32_t L0 = A0 + 8192, B0 = A0 + 16384, B1 = A0 + 24576;             \
        _Pragma("unroll")                                                      \
        for (int i = 0; i < 2; i++) {                                          \
            int r = ur + i * 64;                                               \
            uint32_t d = swz64((uint32_t)(r * 64 + uc * 16));                  \
            CP16(A0 + d, g_Hhi  + (size_t)(m0 + r) * DH + (kt) + uc * 8);      \
            CP16(L0 + d, g_Hlo  + (size_t)(m0 + r) * DH + (kt) + uc * 8);      \
            CP16(B0 + d, g_W2Thi + (size_t)(n0 + r) * DH + (kt) + uc * 8);     \
            CP16(B1 + d, g_W2Tlo + (size_t)(n0 + r) * DH + (kt) + uc * 8);     \
        }                                                                      \
    } while (0)

    G2_PREFETCH(0, 0);  CP_COMMIT();
    G2_PREFETCH(1, 32); CP_COMMIT();

    const int arow  = wm * 32 + (lane & 15);
    const int browb = wn * 64 + ((lane >> 4) << 3) + (lane & 7);

    for (int ck = 0; ck < 64; ck++) {
        CP_WAIT1();
        __syncthreads();
        if (ck + 2 < 64) G2_PREFETCH((ck + 2) % 3, (ck + 2) * 32);
        CP_COMMIT();

        const uint32_t A0 = sb + (ck % 3) * G2_STAGE;
        const uint32_t L0 = A0 + 8192, B0 = A0 + 16384, B1 = A0 + 24576;
        #pragma unroll
        for (int kk = 0; kk < 32; kk += 16) {
            const uint32_t acol = (uint32_t)(kk + (lane >> 4) * 8) * 2;
            const uint32_t bcol = (uint32_t)(kk + ((lane >> 3) & 1) * 8) * 2;
            uint32_t ahi[2][4], alo[2][4], b[4][4];
            LDSM4(ahi[0], A0 + swz64((uint32_t)(arow * 64) + acol));
            LDSM4(ahi[1], A0 + swz64((uint32_t)((arow + 16) * 64) + acol));
            LDSM4(alo[0], L0 + swz64((uint32_t)(arow * 64) + acol));
            LDSM4(alo[1], L0 + swz64((uint32_t)((arow + 16) * 64) + acol));
            #pragma unroll
            for (int j = 0; j < 4; j++)
                LDSM4(b[j], B0 + swz64((uint32_t)((browb + j * 16) * 64) + bcol));
            #pragma unroll
            for (int tm = 0; tm < 2; tm++)
                #pragma unroll
                for (int tn = 0; tn < 8; tn++) {
                    uint32_t* bb = &b[tn >> 1][(tn & 1) * 2];
                    MMA16816(acc[tm][tn], ahi[tm], bb[0], bb[1]);
                    MMA16816(acc[tm][tn], alo[tm], bb[0], bb[1]);
                }
            #pragma unroll
            for (int j = 0; j < 4; j++)
                LDSM4(b[j], B1 + swz64((uint32_t)((browb + j * 16) * 64) + bcol));
            #pragma unroll
            for (int tm = 0; tm < 2; tm++)
                #pragma unroll
                for (int tn = 0; tn < 8; tn++) {
                    uint32_t* bb = &b[tn >> 1][(tn & 1) * 2];
                    MMA16816(acc[tm][tn], ahi[tm], bb[0], bb[1]);
                }
        }
    }

    // ---- epilogue: + b2, direct stores ----
    #pragma unroll
    for (int tm = 0; tm < 2; tm++)
        #pragma unroll
        for (int tn = 0; tn < 8; tn++) {
            int row = m0 + wm * 32 + tm * 16 + (lane >> 2);
            int col = n0 + wn * 64 + tn * 8 + 2 * (lane & 3);
            float bb0 = __ldg(&b2[col]), bb1 = __ldg(&b2[col + 1]);
            *reinterpret_cast<float2*>(&out[(size_t)row * DI + col]) =
                make_float2(acc[tm][tn][0] + bb0, acc[tm][tn][1] + bb1);
            *reinterpret_cast<float2*>(&out[(size_t)(row + 8) * DI + col]) =
                make_float2(acc[tm][tn][2] + bb0, acc[tm][tn][3] + bb1);
        }
    #undef G2_PREFETCH
}

// ---------------------------------------------------------------------------
extern "C" void kernel_launch(void* const* d_in, const int* in_sizes, int n_in,
                              void* d_out, int out_size)
{
    const float* x     = (const float*)d_in[0];
    const float* W1    = (const float*)d_in[1];
    const float* b1    = (const float*)d_in[2];
    const float* W2    = (const float*)d_in[3];
    const float* b2    = (const float*)d_in[4];
    const float* initH = (const float*)d_in[5];
    float* out = (float*)d_out;

    cudaFuncSetAttribute(gemm1_mma_kernel,
                         cudaFuncAttributeMaxDynamicSharedMemorySize, G1_SMEM);
    cudaFuncSetAttribute(gemm2_mma_kernel,
                         cudaFuncAttributeMaxDynamicSharedMemorySize, G2_SMEM);

    split_x_kernel<<<(M_TOT * DI) / (4 * 256), 256>>>(x);
    tsplit_w1_kernel<<<dim3(N1 / 32, DI / 32), dim3(32, 8)>>>(W1);
    tsplit_w2_kernel<<<dim3(DI / 32, DH / 32), dim3(32, 8)>>>(W2);

    gemm1_mma_kernel<<<dim3(DH / 32, M_TOT / 128), 256, G1_SMEM>>>(b1);

    scan_carry_kernel<<<BD / 256, 256>>>(initH, out);
    scan_emit_kernel<<<(NCH * BD) / 256, 256>>>();

    gemm2_mma_kernel<<<dim3(DI / 128, M_TOT / 128), 256, G2_SMEM>>>(b2, out);
}

// round 16
// speedup vs baseline: 2.1311x; 1.0001x over previous
#include <cuda_runtime.h>
#include <cuda_bf16.h>
#include <math.h>
#include <stdint.h>

#define DI    1024
#define DH    2048
#define S_LEN 4096
#define BATCH 4
#define M_TOT (BATCH * S_LEN)   // 16384
#define N1    (3 * DH)          // 6144

#define OUT_ELEMS ((size_t)M_TOT * DI)
#define NH_OFF    OUT_ELEMS
#define NLH_OFF   (OUT_ELEMS + (size_t)BATCH * DH)

#define CHUNK 64
#define NCH   (S_LEN / CHUNK)   // 64
#define BD    (BATCH * DH)      // 8192

// ---------------- static scratch ------------------------------------------
__device__ float         g_C[(size_t)M_TOT * DH];
__device__ float         g_V[(size_t)M_TOT * DH];
__device__ __nv_bfloat16 g_Xhi[(size_t)M_TOT * DI];
__device__ __nv_bfloat16 g_Xlo[(size_t)M_TOT * DI];
__device__ __nv_bfloat16 g_W1Thi[(size_t)N1 * DI];   // [N1][DI]
__device__ __nv_bfloat16 g_W1Tlo[(size_t)N1 * DI];
__device__ __nv_bfloat16 g_Hhi[(size_t)M_TOT * DH];
__device__ __nv_bfloat16 g_Hlo[(size_t)M_TOT * DH];
__device__ __nv_bfloat16 g_W2Thi[(size_t)DI * DH];   // [DI][DH]
__device__ __nv_bfloat16 g_W2Tlo[(size_t)DI * DH];
// scan scratch
__device__ float g_Ak [(size_t)NCH * BD];
__device__ float g_Bk [(size_t)NCH * BD];
__device__ float g_Hin[(size_t)NCH * BD];

// ---------------- math helpers --------------------------------------------
__device__ __forceinline__ float softplusf(float z) {
    return z > 15.f ? z : log1pf(__expf(z));
}
__device__ __forceinline__ float sigmoidf(float z) {
    return 1.f / (1.f + __expf(-z));
}
__device__ __forceinline__ float g_fn(float x) {
    return x >= 0.f ? x + 0.5f : sigmoidf(x);
}
__device__ __forceinline__ void splitf(float a, __nv_bfloat16& hi, __nv_bfloat16& lo) {
    __nv_bfloat16 h = __float2bfloat16(a);
    hi = h;
    lo = __float2bfloat16(a - __bfloat162float(h));
}

// ---------------- PTX helpers ----------------------------------------------
__device__ __forceinline__ uint32_t smem_u32(const void* p) {
    uint32_t a;
    asm("{ .reg .u64 t; cvta.to.shared.u64 t, %1; cvt.u32.u64 %0, t; }"
        : "=r"(a) : "l"(p));
    return a;
}
#define CP16(dst, src) \
    asm volatile("cp.async.cg.shared.global [%0], [%1], 16;" \
                 :: "r"(dst), "l"(src))
#define CP_COMMIT() asm volatile("cp.async.commit_group;" ::: "memory")
#define CP_WAIT0()  asm volatile("cp.async.wait_group 0;" ::: "memory")

template<int N> __device__ __forceinline__ void cp_wait() {
    asm volatile("cp.async.wait_group %0;" :: "n"(N) : "memory");
}

#define LDSM4(r, addr) \
    asm volatile("ldmatrix.sync.aligned.m8n8.x4.shared.b16 {%0,%1,%2,%3}, [%4];" \
        : "=r"((r)[0]), "=r"((r)[1]), "=r"((r)[2]), "=r"((r)[3]) : "r"(addr))

#define MMA16816(d, a, b0v, b1v) \
    asm volatile("mma.sync.aligned.m16n8k16.row.col.f32.bf16.bf16.f32 " \
        "{%0,%1,%2,%3}, {%4,%5,%6,%7}, {%8,%9}, {%0,%1,%2,%3};" \
        : "+f"((d)[0]), "+f"((d)[1]), "+f"((d)[2]), "+f"((d)[3]) \
        : "r"((a)[0]), "r"((a)[1]), "r"((a)[2]), "r"((a)[3]), \
          "r"(b0v), "r"(b1v))

__device__ __forceinline__ uint32_t swz128(uint32_t o) { return o ^ ((o >> 3) & 0x70); }

// ---------------------------------------------------------------------------
// split X -> bf16 hi/lo
// ---------------------------------------------------------------------------
__global__ __launch_bounds__(256) void split_x_kernel(const float* __restrict__ X) {
    size_t i = (size_t)blockIdx.x * 256 + threadIdx.x;
    float4 v = reinterpret_cast<const float4*>(X)[i];
    __nv_bfloat16 h[4], l[4];
    splitf(v.x, h[0], l[0]); splitf(v.y, h[1], l[1]);
    splitf(v.z, h[2], l[2]); splitf(v.w, h[3], l[3]);
    *reinterpret_cast<uint2*>(&g_Xhi[i * 4]) = *reinterpret_cast<uint2*>(h);
    *reinterpret_cast<uint2*>(&g_Xlo[i * 4]) = *reinterpret_cast<uint2*>(l);
}

// ---------------------------------------------------------------------------
// transpose + split  W[R][C] -> T[C][R] bf16 hi/lo
// ---------------------------------------------------------------------------
__device__ __forceinline__ void tsplit_body(const float* __restrict__ W,
                                            __nv_bfloat16* __restrict__ Thi,
                                            __nv_bfloat16* __restrict__ Tlo,
                                            int R, int C) {
    __shared__ float t[32][33];
    int tx = threadIdx.x, ty = threadIdx.y;
    int c0 = blockIdx.x * 32, r0 = blockIdx.y * 32;
    #pragma unroll
    for (int j = 0; j < 32; j += 8)
        t[ty + j][tx] = W[(size_t)(r0 + ty + j) * C + c0 + tx];
    __syncthreads();
    #pragma unroll
    for (int j = 0; j < 32; j += 8) {
        float a = t[tx][ty + j];
        __nv_bfloat16 h, l; splitf(a, h, l);
        size_t o = (size_t)(c0 + ty + j) * R + r0 + tx;
        Thi[o] = h; Tlo[o] = l;
    }
}
__global__ __launch_bounds__(256) void tsplit_w1_kernel(const float* __restrict__ W1) {
    tsplit_body(W1, g_W1Thi, g_W1Tlo, DI, N1);
}
__global__ __launch_bounds__(256) void tsplit_w2_kernel(const float* __restrict__ W2) {
    tsplit_body(W2, g_W2Thi, g_W2Tlo, DH, DI);
}

// ---------------------------------------------------------------------------
// K1: proj = x@W1 (+b1, gate math, chunk-scan fused) -> g_C, g_V, g_Ak, g_Bk
// block 128m x 96n, BK=64, 2-stage cp.async, 256 thr, pass-major MMA order
// stage: Ahi 16K | Alo 16K | Bhi 12K | Blo 12K = 57344 ; x2 = 114688
// ---------------------------------------------------------------------------
#define G1_STAGE 57344
#define G1_SMEM  (2 * G1_STAGE)

__global__ __launch_bounds__(256, 2) void gemm1_mma_kernel(const float* __restrict__ b1) {
    extern __shared__ char sm[];
    const uint32_t sb = smem_u32(sm);
    const int tid = threadIdx.x, lane = tid & 31, wid = tid >> 5;
    const int wm = wid >> 1, wn = wid & 1;
    const int m0 = blockIdx.y * 128, cb0 = blockIdx.x * 32;

    float acc[2][6][4];
    #pragma unroll
    for (int i = 0; i < 2; i++)
        #pragma unroll
        for (int j = 0; j < 6; j++)
            #pragma unroll
            for (int k = 0; k < 4; k++) acc[i][j][k] = 0.f;

    #define G1_PREFETCH(s, kt) do {                                            \
        uint32_t A0_ = sb + (s) * G1_STAGE;                                    \
        uint32_t L0_ = A0_ + 16384, B0_ = A0_ + 32768, B1_ = A0_ + 45056;      \
        _Pragma("unroll")                                                      \
        for (int i = 0; i < 4; i++) {                                          \
            int idx = tid + i * 256;                                           \
            int r = idx >> 3, c = idx & 7;                                     \
            uint32_t d = swz128((uint32_t)(r * 128 + c * 16));                 \
            CP16(A0_ + d, g_Xhi + (size_t)(m0 + r) * DI + (kt) + c * 8);       \
            CP16(L0_ + d, g_Xlo + (size_t)(m0 + r) * DI + (kt) + c * 8);       \
        }                                                                      \
        _Pragma("unroll")                                                      \
        for (int i = 0; i < 3; i++) {                                          \
            int idx = tid + i * 256;                                           \
            int r = idx >> 3, c = idx & 7;                                     \
            int gate = r >> 5, chl = r & 31;                                   \
            size_t row = (size_t)(gate * DH + cb0 + chl) * DI + (kt) + c * 8;  \
            uint32_t d = swz128((uint32_t)(r * 128 + c * 16));                 \
            CP16(B0_ + d, g_W1Thi + row); CP16(B1_ + d, g_W1Tlo + row);        \
        }                                                                      \
    } while (0)

    G1_PREFETCH(0, 0);
    CP_COMMIT();

    const int arow  = wm * 32 + (lane & 15);
    const int browb = wn * 48 + ((lane >> 4) << 3) + (lane & 7);

    for (int ck = 0; ck < 16; ck++) {
        CP_WAIT0();
        __syncthreads();
        if (ck + 1 < 16) {
            G1_PREFETCH((ck + 1) & 1, (ck + 1) * 64);
            CP_COMMIT();
        }
        const uint32_t A0 = sb + (ck & 1) * G1_STAGE;
        const uint32_t L0 = A0 + 16384, B0 = A0 + 32768, B1 = A0 + 45056;
        #pragma unroll
        for (int kk = 0; kk < 64; kk += 16) {
            const uint32_t acol = (uint32_t)(kk + (lane >> 4) * 8) * 2;
            const uint32_t bcol = (uint32_t)(kk + ((lane >> 3) & 1) * 8) * 2;
            uint32_t ahi[2][4], alo[2][4], bhi[3][4], blo[3][4];
            LDSM4(ahi[0], A0 + swz128((uint32_t)(arow * 128) + acol));
            LDSM4(ahi[1], A0 + swz128((uint32_t)((arow + 16) * 128) + acol));
            LDSM4(alo[0], L0 + swz128((uint32_t)(arow * 128) + acol));
            LDSM4(alo[1], L0 + swz128((uint32_t)((arow + 16) * 128) + acol));
            #pragma unroll
            for (int j = 0; j < 3; j++) {
                LDSM4(bhi[j], B0 + swz128((uint32_t)((browb + j * 16) * 128) + bcol));
                LDSM4(blo[j], B1 + swz128((uint32_t)((browb + j * 16) * 128) + bcol));
            }
            // pass-major: 12 independent MMAs per pass; per-acc order preserved
            #pragma unroll
            for (int tm = 0; tm < 2; tm++)
                #pragma unroll
                for (int tn = 0; tn < 6; tn++)
                    MMA16816(acc[tm][tn], ahi[tm],
                             bhi[tn >> 1][(tn & 1) * 2], bhi[tn >> 1][(tn & 1) * 2 + 1]);
            #pragma unroll
            for (int tm = 0; tm < 2; tm++)
                #pragma unroll
                for (int tn = 0; tn < 6; tn++)
                    MMA16816(acc[tm][tn], ahi[tm],
                             blo[tn >> 1][(tn & 1) * 2], blo[tn >> 1][(tn & 1) * 2 + 1]);
            #pragma unroll
            for (int tm = 0; tm < 2; tm++)
                #pragma unroll
                for (int tn = 0; tn < 6; tn++)
                    MMA16816(acc[tm][tn], alo[tm],
                             bhi[tn >> 1][(tn & 1) * 2], bhi[tn >> 1][(tn & 1) * 2 + 1]);
        }
    }
    __syncthreads();

    // ---- epilogue: acc -> proj smem -> gate math -> g_C/g_V + chunk scan ----
    float* proj = reinterpret_cast<float*>(sm);     // [128][100] = 51200 B
    #pragma unroll
    for (int tm = 0; tm < 2; tm++)
        #pragma unroll
        for (int tn = 0; tn < 6; tn++) {
            int row = wm * 32 + tm * 16 + (lane >> 2);
            int col = wn * 48 + tn * 8 + 2 * (lane & 3);
            *reinterpret_cast<float2*>(&proj[row * 100 + col]) =
                make_float2(acc[tm][tn][0], acc[tm][tn][1]);
            *reinterpret_cast<float2*>(&proj[(row + 8) * 100 + col]) =
                make_float2(acc[tm][tn][2], acc[tm][tn][3]);
        }
    __syncthreads();

    const int ch = tid & 31;
    const int seg = tid >> 5;                        // 8 segments of 16 rows
    const float bh = __ldg(&b1[cb0 + ch]);
    const float bf = __ldg(&b1[DH + cb0 + ch]);
    const float bi = __ldg(&b1[2 * DH + cb0 + ch]);
    float Aa = 1.f, Bb = 0.f;
    #pragma unroll
    for (int j = 0; j < 16; j++) {
        int row = seg * 16 + j;                      // sequential in time
        float hid = proj[row * 100 + ch] + bh;
        float fg  = proj[row * 100 + 32 + ch] + bf;
        float ig  = proj[row * 100 + 64 + ch] + bi;
        float diff = softplusf(-fg) - softplusf(-ig);
        float c = sigmoidf(-diff);
        float v = sigmoidf(diff) * g_fn(hid);
        size_t o = (size_t)(m0 + row) * DH + cb0 + ch;
        g_C[o] = c;
        g_V[o] = v;
        Aa *= c;
        Bb = fmaf(c, Bb, v);
    }
    float* pA = reinterpret_cast<float*>(sm + 51200);   // [8][32]
    float* pB = pA + 256;
    pA[seg * 32 + ch] = Aa;
    pB[seg * 32 + ch] = Bb;
    __syncthreads();
    if (tid < 64) {
        int cl = tid >> 5, c2 = tid & 31;            // 2 chunks x 32 channels
        float A = 1.f, Bv = 0.f;
        #pragma unroll
        for (int s2 = 0; s2 < 4; s2++) {
            int i2 = (cl * 4 + s2) * 32 + c2;
            float As = pA[i2], Bs = pB[i2];
            A = As * A;
            Bv = fmaf(As, Bv, Bs);
        }
        int b     = m0 / S_LEN;
        int chunk = (m0 % S_LEN) / CHUNK + cl;
        size_t t = (size_t)chunk * BD + (size_t)b * DH + cb0 + c2;
        g_Ak[t] = A;
        g_Bk[t] = Bv;
    }
    #undef G1_PREFETCH
}

// ---------------------------------------------------------------------------
// scan carry + emit
// ---------------------------------------------------------------------------
__global__ __launch_bounds__(256) void scan_carry_kernel(
    const float* __restrict__ initH, float* __restrict__ out)
{
    int bd = blockIdx.x * 256 + threadIdx.x;         // b*DH + d
    int d = bd & (DH - 1);
    float h = g_fn(initH[d]);
    #pragma unroll 8
    for (int ch = 0; ch < NCH; ch++) {
        int t = ch * BD + bd;
        g_Hin[t] = h;
        h = fmaf(g_Ak[t], h, g_Bk[t]);
    }
    out[NH_OFF  + bd] = h;
    out[NLH_OFF + bd] = logf(h);
}

__global__ __launch_bounds__(256) void scan_emit_kernel() {
    int t = blockIdx.x * 256 + threadIdx.x;
    int bd = t & (BD - 1);
    int chunk = t >> 13;
    int b = bd >> 11, d = bd & (DH - 1);
    size_t base = ((size_t)b * S_LEN + (size_t)chunk * CHUNK) * DH + d;
    float h = g_Hin[t];
    #pragma unroll 8
    for (int s = 0; s < CHUNK; s++) {
        size_t idx = base + (size_t)s * DH;
        h = fmaf(g_C[idx], h, g_V[idx]);
        __nv_bfloat16 hh, hl; splitf(h, hh, hl);
        g_Hhi[idx] = hh; g_Hlo[idx] = hl;
    }
}

// ---------------------------------------------------------------------------
// K3: out = h@W2 + b2
// block 128m x 128n, BK=64, 3-stage cp.async, 256 thr, 1 CTA/SM
// stage: Ahi 16K | Alo 16K | Bhi 16K | Blo 16K = 65536 ; x3 = 196608
// ---------------------------------------------------------------------------
#define G2_STAGE 65536
#define G2_SMEM  (3 * G2_STAGE)

__global__ __launch_bounds__(256, 1) void gemm2_mma_kernel(
    const float* __restrict__ b2, float* __restrict__ out)
{
    extern __shared__ char sm[];
    const uint32_t sb = smem_u32(sm);
    const int tid = threadIdx.x, lane = tid & 31, wid = tid >> 5;
    const int wm = wid >> 1, wn = wid & 1;
    const int m0 = blockIdx.y * 128, n0 = blockIdx.x * 128;

    float acc[2][8][4];
    #pragma unroll
    for (int i = 0; i < 2; i++)
        #pragma unroll
        for (int j = 0; j < 8; j++)
            #pragma unroll
            for (int k = 0; k < 4; k++) acc[i][j][k] = 0.f;

    #define G2_PREFETCH(s, kt) do {                                            \
        uint32_t A0_ = sb + (s) * G2_STAGE;                                    \
        uint32_t L0_ = A0_ + 16384, B0_ = A0_ + 32768, B1_ = A0_ + 49152;      \
        _Pragma("unroll")                                                      \
        for (int i = 0; i < 4; i++) {                                          \
            int idx = tid + i * 256;                                           \
            int r = idx >> 3, c = idx & 7;                                     \
            uint32_t d = swz128((uint32_t)(r * 128 + c * 16));                 \
            CP16(A0_ + d, g_Hhi   + (size_t)(m0 + r) * DH + (kt) + c * 8);     \
            CP16(L0_ + d, g_Hlo   + (size_t)(m0 + r) * DH + (kt) + c * 8);     \
            CP16(B0_ + d, g_W2Thi + (size_t)(n0 + r) * DH + (kt) + c * 8);     \
            CP16(B1_ + d, g_W2Tlo + (size_t)(n0 + r) * DH + (kt) + c * 8);     \
        }                                                                      \
    } while (0)

    G2_PREFETCH(0, 0);  CP_COMMIT();
    G2_PREFETCH(1, 64); CP_COMMIT();

    const int arow  = wm * 32 + (lane & 15);
    const int browb = wn * 64 + ((lane >> 4) << 3) + (lane & 7);

    for (int ck = 0; ck < 32; ck++) {
        cp_wait<1>();               // stage ck complete; stage ck+1 may fly
        __syncthreads();            // all threads' waits done; buf (ck+2)%3 free
        if (ck + 2 < 32) {
            G2_PREFETCH((ck + 2) % 3, (ck + 2) * 64);
            CP_COMMIT();
        } else {
            CP_COMMIT();            // empty group keeps wait accounting exact
        }
        const uint32_t A0 = sb + (ck % 3) * G2_STAGE;
        const uint32_t L0 = A0 + 16384, B0 = A0 + 32768, B1 = A0 + 49152;
        #pragma unroll
        for (int kk = 0; kk < 64; kk += 16) {
            const uint32_t acol = (uint32_t)(kk + (lane >> 4) * 8) * 2;
            const uint32_t bcol = (uint32_t)(kk + ((lane >> 3) & 1) * 8) * 2;
            uint32_t ahi[2][4], alo[2][4], b[4][4];
            LDSM4(ahi[0], A0 + swz128((uint32_t)(arow * 128) + acol));
            LDSM4(ahi[1], A0 + swz128((uint32_t)((arow + 16) * 128) + acol));
            LDSM4(alo[0], L0 + swz128((uint32_t)(arow * 128) + acol));
            LDSM4(alo[1], L0 + swz128((uint32_t)((arow + 16) * 128) + acol));
            #pragma unroll
            for (int j = 0; j < 4; j++)
                LDSM4(b[j], B0 + swz128((uint32_t)((browb + j * 16) * 128) + bcol));
            // pass-major: 16 independent MMAs per pass; per-acc order preserved
            #pragma unroll
            for (int tm = 0; tm < 2; tm++)
                #pragma unroll
                for (int tn = 0; tn < 8; tn++)
                    MMA16816(acc[tm][tn], ahi[tm],
                             b[tn >> 1][(tn & 1) * 2], b[tn >> 1][(tn & 1) * 2 + 1]);
            #pragma unroll
            for (int tm = 0; tm < 2; tm++)
                #pragma unroll
                for (int tn = 0; tn < 8; tn++)
                    MMA16816(acc[tm][tn], alo[tm],
                             b[tn >> 1][(tn & 1) * 2], b[tn >> 1][(tn & 1) * 2 + 1]);
            #pragma unroll
            for (int j = 0; j < 4; j++)
                LDSM4(b[j], B1 + swz128((uint32_t)((browb + j * 16) * 128) + bcol));
            #pragma unroll
            for (int tm = 0; tm < 2; tm++)
                #pragma unroll
                for (int tn = 0; tn < 8; tn++)
                    MMA16816(acc[tm][tn], ahi[tm],
                             b[tn >> 1][(tn & 1) * 2], b[tn >> 1][(tn & 1) * 2 + 1]);
        }
    }

    // ---- epilogue: + b2, direct stores ----
    #pragma unroll
    for (int tm = 0; tm < 2; tm++)
        #pragma unroll
        for (int tn = 0; tn < 8; tn++) {
            int row = m0 + wm * 32 + tm * 16 + (lane >> 2);
            int col = n0 + wn * 64 + tn * 8 + 2 * (lane & 3);
            float bb0 = __ldg(&b2[col]), bb1 = __ldg(&b2[col + 1]);
            *reinterpret_cast<float2*>(&out[(size_t)row * DI + col]) =
                make_float2(acc[tm][tn][0] + bb0, acc[tm][tn][1] + bb1);
            *reinterpret_cast<float2*>(&out[(size_t)(row + 8) * DI + col]) =
                make_float2(acc[tm][tn][2] + bb0, acc[tm][tn][3] + bb1);
        }
    #undef G2_PREFETCH
}

// ---------------------------------------------------------------------------
extern "C" void kernel_launch(void* const* d_in, const int* in_sizes, int n_in,
                              void* d_out, int out_size)
{
    const float* x     = (const float*)d_in[0];
    const float* W1    = (const float*)d_in[1];
    const float* b1    = (const float*)d_in[2];
    const float* W2    = (const float*)d_in[3];
    const float* b2    = (const float*)d_in[4];
    const float* initH = (const float*)d_in[5];
    float* out = (float*)d_out;

    cudaFuncSetAttribute(gemm1_mma_kernel,
                         cudaFuncAttributeMaxDynamicSharedMemorySize, G1_SMEM);
    cudaFuncSetAttribute(gemm2_mma_kernel,
                         cudaFuncAttributeMaxDynamicSharedMemorySize, G2_SMEM);

    split_x_kernel<<<(M_TOT * DI) / (4 * 256), 256>>>(x);
    tsplit_w1_kernel<<<dim3(N1 / 32, DI / 32), dim3(32, 8)>>>(W1);
    tsplit_w2_kernel<<<dim3(DI / 32, DH / 32), dim3(32, 8)>>>(W2);

    gemm1_mma_kernel<<<dim3(DH / 32, M_TOT / 128), 256, G1_SMEM>>>(b1);

    scan_carry_kernel<<<BD / 256, 256>>>(initH, out);
    scan_emit_kernel<<<(NCH * BD) / 256, 256>>>();

    gemm2_mma_kernel<<<dim3(DI / 128, M_TOT / 128), 256, G2_SMEM>>>(b2, out);
}